// round 2
// baseline (speedup 1.0000x reference)
#include <cuda_runtime.h>
#include <cstdint>

#define NN 100000
#define NE 1600000
#define F_IN 256
#define HID 128
#define OUTF 64

// ---------------- scratch (device globals; no allocation allowed) ----------
__device__ float g_deg[NN];
__device__ float g_isq[NN];          // deg^-1/2  (norm1)
__device__ float g_inv[NN];          // deg^-1    (norm2)
__device__ float g_m1[NN * HID];     // mean1 -> msg m1 -> reused as h2_mean
__device__ float g_v1[NN * HID];     // var1  -> msg v1 -> reused as h2_var
__device__ float g_a1m[NN * HID];    // aggregated mean, layer 1
__device__ float g_a1v[NN * HID];
__device__ float g_m2[NN * OUTF];
__device__ float g_v2[NN * OUTF];
__device__ float g_a2m[NN * OUTF];
__device__ float g_a2v[NN * OUTF];

// ---------------- init: zero deg + all accumulators ------------------------
__global__ void zero_all_kernel() {
    const size_t n_deg = NN / 4;
    const size_t n_h   = (size_t)NN * HID / 4;
    const size_t n_o   = (size_t)NN * OUTF / 4;
    const size_t total = n_deg + 2 * n_h + 2 * n_o;
    const float4 z = make_float4(0.f, 0.f, 0.f, 0.f);
    for (size_t i = (size_t)blockIdx.x * blockDim.x + threadIdx.x;
         i < total; i += (size_t)gridDim.x * blockDim.x) {
        size_t r = i;
        if (r < n_deg) { reinterpret_cast<float4*>(g_deg)[r] = z; continue; }
        r -= n_deg;
        if (r < n_h) { reinterpret_cast<float4*>(g_a1m)[r] = z; continue; }
        r -= n_h;
        if (r < n_h) { reinterpret_cast<float4*>(g_a1v)[r] = z; continue; }
        r -= n_h;
        if (r < n_o) { reinterpret_cast<float4*>(g_a2m)[r] = z; continue; }
        r -= n_o;
        reinterpret_cast<float4*>(g_a2v)[r] = z;
    }
}

// ---------------- degrees & norms ------------------------------------------
__global__ void deg_kernel(const int* __restrict__ dst) {
    int e = blockIdx.x * blockDim.x + threadIdx.x;
    if (e < NE) atomicAdd(&g_deg[dst[e]], 1.0f);
}

__global__ void norm_kernel() {
    int i = blockIdx.x * blockDim.x + threadIdx.x;
    if (i < NN) {
        float d = fmaxf(g_deg[i], 1.0f);
        float is = 1.0f / sqrtf(d);
        g_isq[i] = is;
        g_inv[i] = is * is;
    }
}

// ---------------- fp32 SGEMM with bias + relu ------------------------------
template <int BM, int BN, int BK, int TM, int TN>
__global__ void __launch_bounds__(256, 2)
sgemm_bias_relu(const float* __restrict__ A, const float* __restrict__ W,
                const float* __restrict__ bias, float* __restrict__ C,
                int M, int K, int N) {
    constexpr int TX = BN / TN;
    constexpr int TY = BM / TM;
    static_assert(TX * TY == 256, "block must be 256 threads");
    __shared__ float As[BK][BM + 1];
    __shared__ float Bs[BK][BN];

    const int tid = threadIdx.x;
    const int tx = tid % TX;
    const int ty = tid / TX;
    const int row0 = blockIdx.x * BM;

    constexpr int AROWS = 256 * 4 / BK;
    constexpr int APASS = BM / AROWS;
    const int a_r = tid / (BK / 4);
    const int a_c = (tid % (BK / 4)) * 4;

    constexpr int BROWS = 256 * 4 / BN;
    constexpr int BPASS = BK / BROWS;
    const int b_r = tid / (BN / 4);
    const int b_c = (tid % (BN / 4)) * 4;

    float acc[TM][TN];
#pragma unroll
    for (int i = 0; i < TM; i++)
#pragma unroll
        for (int j = 0; j < TN; j++) acc[i][j] = 0.f;

    for (int k0 = 0; k0 < K; k0 += BK) {
#pragma unroll
        for (int p = 0; p < APASS; p++) {
            int r = a_r + p * AROWS;
            int gr = row0 + r;
            float4 v = make_float4(0.f, 0.f, 0.f, 0.f);
            if (gr < M)
                v = *reinterpret_cast<const float4*>(&A[(size_t)gr * K + k0 + a_c]);
            As[a_c + 0][r] = v.x;
            As[a_c + 1][r] = v.y;
            As[a_c + 2][r] = v.z;
            As[a_c + 3][r] = v.w;
        }
#pragma unroll
        for (int p = 0; p < BPASS; p++) {
            int r = b_r + p * BROWS;
            *reinterpret_cast<float4*>(&Bs[r][b_c]) =
                *reinterpret_cast<const float4*>(&W[(size_t)(k0 + r) * N + b_c]);
        }
        __syncthreads();
#pragma unroll
        for (int k = 0; k < BK; k++) {
            float ar[TM], br[TN];
#pragma unroll
            for (int i = 0; i < TM; i++) ar[i] = As[k][ty * TM + i];
#pragma unroll
            for (int j = 0; j < TN; j++) br[j] = Bs[k][tx * TN + j];
#pragma unroll
            for (int i = 0; i < TM; i++)
#pragma unroll
                for (int j = 0; j < TN; j++)
                    acc[i][j] = fmaf(ar[i], br[j], acc[i][j]);
        }
        __syncthreads();
    }

#pragma unroll
    for (int i = 0; i < TM; i++) {
        int gr = row0 + ty * TM + i;
        if (gr >= M) continue;
#pragma unroll
        for (int j = 0; j < TN; j += 4) {
            int c = tx * TN + j;
            float4 o;
            o.x = fmaxf(acc[i][j + 0] + bias[c + 0], 0.f);
            o.y = fmaxf(acc[i][j + 1] + bias[c + 1], 0.f);
            o.z = fmaxf(acc[i][j + 2] + bias[c + 2], 0.f);
            o.w = fmaxf(acc[i][j + 3] + bias[c + 3], 0.f);
            *reinterpret_cast<float4*>(&C[(size_t)gr * N + c]) = o;
        }
    }
}

// ---------------- message transform (in place) -----------------------------
template <int D>
__global__ void msg_kernel(float* __restrict__ mbuf, float* __restrict__ vbuf) {
    size_t idx = (size_t)blockIdx.x * blockDim.x + threadIdx.x;
    if (idx >= (size_t)NN * D) return;
    int i = (int)(idx / D);
    float mean = mbuf[idx];
    float var = vbuf[idx];
    float att = expf(-var);
    mbuf[idx] = mean * att * g_isq[i];
    vbuf[idx] = var * att * att * g_inv[i];
}

// ---------------- edge aggregation (layer 1: 128 dims) ---------------------
__device__ __forceinline__ void red_v4(float* p, float4 v) {
    asm volatile("red.global.add.v4.f32 [%0], {%1,%2,%3,%4};"
                 :: "l"(p), "f"(v.x), "f"(v.y), "f"(v.z), "f"(v.w)
                 : "memory");
}

__global__ void agg1_kernel(const int* __restrict__ src, const int* __restrict__ dst) {
    int warp = (blockIdx.x * blockDim.x + threadIdx.x) >> 5;
    int lane = threadIdx.x & 31;
    if (warp >= NE) return;
    int s = __ldg(&src[warp]);
    int d = __ldg(&dst[warp]);
    size_t so = (size_t)s * HID + lane * 4;
    size_t dofs = (size_t)d * HID + lane * 4;
    float4 m = *reinterpret_cast<const float4*>(&g_m1[so]);
    red_v4(&g_a1m[dofs], m);
    float4 v = *reinterpret_cast<const float4*>(&g_v1[so]);
    red_v4(&g_a1v[dofs], v);
}

__global__ void post1_kernel() {
    size_t idx = (size_t)blockIdx.x * blockDim.x + threadIdx.x;
    if (idx >= (size_t)NN * HID) return;
    int i = (int)(idx / HID);
    g_m1[idx] = fmaxf(g_a1m[idx] * g_isq[i], 0.f);
    g_v1[idx] = fmaxf(g_a1v[idx] * g_inv[i], 0.f);
}

// ---------------- edge aggregation (layer 2: 64 dims) ----------------------
__global__ void agg2_kernel(const int* __restrict__ src, const int* __restrict__ dst) {
    int warp = (blockIdx.x * blockDim.x + threadIdx.x) >> 5;
    int lane = threadIdx.x & 31;
    if (warp >= NE) return;
    int s = __ldg(&src[warp]);
    int d = __ldg(&dst[warp]);
    bool isv = lane >= 16;
    int c = (lane & 15) * 4;
    const float* sb = isv ? g_v2 : g_m2;
    float* db = isv ? g_a2v : g_a2m;
    float4 m = *reinterpret_cast<const float4*>(&sb[(size_t)s * OUTF + c]);
    red_v4(&db[(size_t)d * OUTF + c], m);
}

// ---------------- threefry-2x32 (JAX partitionable mode) -------------------
// JAX >= 0.5 defaults jax_threefry_partitionable=True:
//   per element i: (b1,b2) = threefry2x32(key=(0,42), counts=(hi32(i), lo32(i)))
//   32-bit draw = b1 ^ b2      (jax/_src/prng.py::_threefry_random_bits_partitionable)
__device__ __forceinline__ uint32_t rotl32(uint32_t x, int r) {
    return __funnelshift_l(x, x, r);
}

__device__ __forceinline__ void threefry_42(uint32_t x0, uint32_t x1,
                                            uint32_t& o0, uint32_t& o1) {
    const uint32_t k0 = 0u, k1 = 42u;
    const uint32_t k2 = k0 ^ k1 ^ 0x1BD11BDAu;
    x0 += k0; x1 += k1;
#define TF_R4(a, b, c, d)                              \
    x0 += x1; x1 = rotl32(x1, a); x1 ^= x0;            \
    x0 += x1; x1 = rotl32(x1, b); x1 ^= x0;            \
    x0 += x1; x1 = rotl32(x1, c); x1 ^= x0;            \
    x0 += x1; x1 = rotl32(x1, d); x1 ^= x0;
    TF_R4(13, 15, 26, 6)  x0 += k1; x1 += k2 + 1u;
    TF_R4(17, 29, 16, 24) x0 += k2; x1 += k0 + 2u;
    TF_R4(13, 15, 26, 6)  x0 += k0; x1 += k1 + 3u;
    TF_R4(17, 29, 16, 24) x0 += k1; x1 += k2 + 4u;
    TF_R4(13, 15, 26, 6)  x0 += k2; x1 += k0 + 5u;
#undef TF_R4
    o0 = x0; o1 = x1;
}

__device__ __forceinline__ float bits_to_normal(uint32_t b) {
    // bits -> [0,1): bitcast((b>>9)|0x3f800000) - 1
    // uniform to [lo,1): scale = (1 - lo) rounds to exactly 2.0f, and *2.0 is
    // exact, so fmaf == JAX's separate mul+add.
    float f = __uint_as_float((b >> 9) | 0x3F800000u) - 1.0f;
    const float LO = -0.99999994f;   // nextafter(-1, 0)
    float u = fmaf(f, 2.0f, LO);
    u = fmaxf(u, LO);
    return 1.41421356f * erfinvf(u);
}

__device__ __forceinline__ float final_val(int f, float eps) {
    int i = f >> 6;  // / OUTF
    float mean = g_a2m[f] * g_isq[i];
    float var = g_a2v[f] * g_inv[i];
    return fmaf(eps, sqrtf(var + 1e-8f), mean);
}

__global__ void final_kernel(float* __restrict__ out) {
    const int total = NN * OUTF;  // 6,400,000 (< 2^32, so hi counter = 0)
    int j = blockIdx.x * blockDim.x + threadIdx.x;
    if (j >= total) return;
    uint32_t o0, o1;
    threefry_42(0u, (uint32_t)j, o0, o1);
    uint32_t bits = o0 ^ o1;   // partitionable 32-bit draw
    out[j] = final_val(j, bits_to_normal(bits));
}

// ---------------- launch ----------------------------------------------------
extern "C" void kernel_launch(void* const* d_in, const int* in_sizes, int n_in,
                              void* d_out, int out_size) {
    const float* x   = (const float*)d_in[0];
    const int* src   = (const int*)d_in[1];
    const int* dst   = (const int*)d_in[2];
    const float* wm1 = (const float*)d_in[3];
    const float* wv1 = (const float*)d_in[4];
    const float* bm1 = (const float*)d_in[5];
    const float* bv1 = (const float*)d_in[6];
    const float* wm2 = (const float*)d_in[7];
    const float* wv2 = (const float*)d_in[8];
    const float* bm2 = (const float*)d_in[9];
    const float* bv2 = (const float*)d_in[10];
    float* out = (float*)d_out;

    (void)in_sizes; (void)n_in; (void)out_size;

    float *p_m1, *p_v1, *p_m2, *p_v2;
    cudaGetSymbolAddress((void**)&p_m1, g_m1);
    cudaGetSymbolAddress((void**)&p_v1, g_v1);
    cudaGetSymbolAddress((void**)&p_m2, g_m2);
    cudaGetSymbolAddress((void**)&p_v2, g_v2);

    zero_all_kernel<<<4096, 256>>>();

    deg_kernel<<<(NE + 255) / 256, 256>>>(dst);
    norm_kernel<<<(NN + 255) / 256, 256>>>();

    const int gx1 = (NN + 127) / 128;
    sgemm_bias_relu<128, 128, 16, 8, 8><<<gx1, 256>>>(x, wm1, bm1, p_m1, NN, F_IN, HID);
    sgemm_bias_relu<128, 128, 16, 8, 8><<<gx1, 256>>>(x, wv1, bv1, p_v1, NN, F_IN, HID);

    msg_kernel<HID><<<(NN * HID + 255) / 256, 256>>>(p_m1, p_v1);

    agg1_kernel<<<NE / 8, 256>>>(src, dst);

    post1_kernel<<<(NN * HID + 255) / 256, 256>>>();

    sgemm_bias_relu<128, 64, 16, 8, 4><<<gx1, 256>>>(p_m1, wm2, bm2, p_m2, NN, HID, OUTF);
    sgemm_bias_relu<128, 64, 16, 8, 4><<<gx1, 256>>>(p_v1, wv2, bv2, p_v2, NN, HID, OUTF);

    msg_kernel<OUTF><<<(NN * OUTF + 255) / 256, 256>>>(p_m2, p_v2);

    agg2_kernel<<<NE / 8, 256>>>(src, dst);

    final_kernel<<<(NN * OUTF + 255) / 256, 256>>>(out);
}

// round 3
// speedup vs baseline: 1.1725x; 1.1725x over previous
#include <cuda_runtime.h>
#include <cstdint>

#define NN 100000
#define NE 1600000
#define F_IN 256
#define HID 128
#define OUTF 64

// ---------------- scratch (device globals; no allocation allowed) ----------
__device__ float g_deg[NN];
__device__ float g_isq[NN];          // deg^-1/2  (norm1)
__device__ float g_inv[NN];          // deg^-1    (norm2)
__device__ float g_m1[NN * HID];     // msg m1 -> reused as h2_mean
__device__ float g_v1[NN * HID];     // msg v1 -> reused as h2_var
__device__ float g_a1m[NN * HID];
__device__ float g_a1v[NN * HID];
__device__ float g_m2[NN * OUTF];
__device__ float g_v2[NN * OUTF];
__device__ float g_a2m[NN * OUTF];
__device__ float g_a2v[NN * OUTF];

// ---------------- init ------------------------------------------------------
__global__ void zero_all_kernel() {
    const size_t n_deg = NN / 4;
    const size_t n_h   = (size_t)NN * HID / 4;
    const size_t n_o   = (size_t)NN * OUTF / 4;
    const size_t total = n_deg + 2 * n_h + 2 * n_o;
    const float4 z = make_float4(0.f, 0.f, 0.f, 0.f);
    for (size_t i = (size_t)blockIdx.x * blockDim.x + threadIdx.x;
         i < total; i += (size_t)gridDim.x * blockDim.x) {
        size_t r = i;
        if (r < n_deg) { reinterpret_cast<float4*>(g_deg)[r] = z; continue; }
        r -= n_deg;
        if (r < n_h) { reinterpret_cast<float4*>(g_a1m)[r] = z; continue; }
        r -= n_h;
        if (r < n_h) { reinterpret_cast<float4*>(g_a1v)[r] = z; continue; }
        r -= n_h;
        if (r < n_o) { reinterpret_cast<float4*>(g_a2m)[r] = z; continue; }
        r -= n_o;
        reinterpret_cast<float4*>(g_a2v)[r] = z;
    }
}

__global__ void deg_kernel(const int* __restrict__ dst) {
    int e = blockIdx.x * blockDim.x + threadIdx.x;
    if (e < NE) atomicAdd(&g_deg[dst[e]], 1.0f);
}

__global__ void norm_kernel() {
    int i = blockIdx.x * blockDim.x + threadIdx.x;
    if (i < NN) {
        float d = fmaxf(g_deg[i], 1.0f);
        float is = 1.0f / sqrtf(d);
        g_isq[i] = is;
        g_inv[i] = is * is;
    }
}

// ---------------- cp.async helpers -----------------------------------------
__device__ __forceinline__ void cp_async16(void* smem, const void* gmem) {
    uint32_t s = (uint32_t)__cvta_generic_to_shared(smem);
    asm volatile("cp.async.ca.shared.global [%0], [%1], 16;" :: "r"(s), "l"(gmem));
}
__device__ __forceinline__ void cp_commit() {
    asm volatile("cp.async.commit_group;");
}
__device__ __forceinline__ void cp_wait0() {
    asm volatile("cp.async.wait_group 0;");
}

// ---------------- fused dual GEMM + message-transform epilogue -------------
// Computes mean = relu(Am@Wm + bm), var = relu(Av@Wv + bv) in one pass, then
// att = exp(-var) and writes Cm = mean*att*isq[row], Cv = var*att^2*inv[row].
// Double-buffered: B tiles via cp.async, A tiles via register staging.
template <int BM, int BN, int BK, int TM, int TN, bool SAME_A>
__global__ void __launch_bounds__(256, 2)
gemm_dual_msg(const float* __restrict__ Am, const float* __restrict__ Av,
              const float* __restrict__ Wm, const float* __restrict__ Wv,
              const float* __restrict__ biasm, const float* __restrict__ biasv,
              float* __restrict__ Cm, float* __restrict__ Cv,
              int M, int K, int N) {
    constexpr int TX = BN / TN;
    constexpr int TY = BM / TM;
    static_assert(TX * TY == 256, "256 threads");
    static_assert(BK * BN / 4 == 256, "one float4 per thread per B tile");
    static_assert((BM + 4) % 4 == 0, "");

    __shared__ float Asm[2][BK][BM + 4];
    __shared__ float Asv[SAME_A ? 1 : 2][BK][SAME_A ? 1 : (BM + 4)];
    __shared__ float Bsm[2][BK][BN];
    __shared__ float Bsv[2][BK][BN];

    const int tid = threadIdx.x;
    const int tx = tid % TX;
    const int ty = tid / TX;
    const int row0 = blockIdx.x * BM;
    const int col0 = blockIdx.y * BN;

    constexpr int AROWS = 256 / (BK / 4);   // rows per load pass
    constexpr int APASS = BM / AROWS;
    const int a_r = tid / (BK / 4);
    const int a_c = (tid % (BK / 4)) * 4;

    const int b_r = tid / (BN / 4);
    const int b_c = (tid % (BN / 4)) * 4;

    float4 pam[APASS], pav[APASS];

    auto fetchA = [&](int k0) {
        const float4 z = make_float4(0.f, 0.f, 0.f, 0.f);
#pragma unroll
        for (int p = 0; p < APASS; p++) {
            int gr = row0 + a_r + p * AROWS;
            pam[p] = (gr < M)
                ? *reinterpret_cast<const float4*>(&Am[(size_t)gr * K + k0 + a_c]) : z;
            if constexpr (!SAME_A)
                pav[p] = (gr < M)
                    ? *reinterpret_cast<const float4*>(&Av[(size_t)gr * K + k0 + a_c]) : z;
        }
    };
    auto stsA = [&](int buf) {
#pragma unroll
        for (int p = 0; p < APASS; p++) {
            int r = a_r + p * AROWS;
            Asm[buf][a_c + 0][r] = pam[p].x;
            Asm[buf][a_c + 1][r] = pam[p].y;
            Asm[buf][a_c + 2][r] = pam[p].z;
            Asm[buf][a_c + 3][r] = pam[p].w;
            if constexpr (!SAME_A) {
                Asv[buf][a_c + 0][r] = pav[p].x;
                Asv[buf][a_c + 1][r] = pav[p].y;
                Asv[buf][a_c + 2][r] = pav[p].z;
                Asv[buf][a_c + 3][r] = pav[p].w;
            }
        }
    };
    auto fetchB = [&](int k0, int buf) {
        cp_async16(&Bsm[buf][b_r][b_c], &Wm[(size_t)(k0 + b_r) * N + col0 + b_c]);
        cp_async16(&Bsv[buf][b_r][b_c], &Wv[(size_t)(k0 + b_r) * N + col0 + b_c]);
        cp_commit();
    };

    float accm[TM][TN], accv[TM][TN];
#pragma unroll
    for (int i = 0; i < TM; i++)
#pragma unroll
        for (int j = 0; j < TN; j++) { accm[i][j] = 0.f; accv[i][j] = 0.f; }

    const int STEPS = K / BK;
    fetchA(0);
    fetchB(0, 0);
    stsA(0);
    cp_wait0();
    __syncthreads();

    int buf = 0;
    for (int s = 0; s < STEPS; s++) {
        if (s + 1 < STEPS) {
            fetchB((s + 1) * BK, buf ^ 1);
            fetchA((s + 1) * BK);
        }
#pragma unroll
        for (int k = 0; k < BK; k++) {
            float arm[TM], arv[TM];
#pragma unroll
            for (int i = 0; i < TM; i += 4)
                *reinterpret_cast<float4*>(&arm[i]) =
                    *reinterpret_cast<const float4*>(&Asm[buf][k][ty * TM + i]);
            if constexpr (!SAME_A) {
#pragma unroll
                for (int i = 0; i < TM; i += 4)
                    *reinterpret_cast<float4*>(&arv[i]) =
                        *reinterpret_cast<const float4*>(&Asv[buf][k][ty * TM + i]);
            }
            float4 bm4 = *reinterpret_cast<const float4*>(&Bsm[buf][k][tx * TN]);
            float4 bv4 = *reinterpret_cast<const float4*>(&Bsv[buf][k][tx * TN]);
            const float* bmp = reinterpret_cast<const float*>(&bm4);
            const float* bvp = reinterpret_cast<const float*>(&bv4);
#pragma unroll
            for (int i = 0; i < TM; i++) {
                float am = arm[i];
                float av = SAME_A ? arm[i] : arv[i];
#pragma unroll
                for (int j = 0; j < TN; j++) {
                    accm[i][j] = fmaf(am, bmp[j], accm[i][j]);
                    accv[i][j] = fmaf(av, bvp[j], accv[i][j]);
                }
            }
        }
        if (s + 1 < STEPS) {
            stsA(buf ^ 1);
            cp_wait0();
            __syncthreads();
            buf ^= 1;
        }
    }

    // epilogue: bias + relu + attention reweight + src-norm prescale
    float bmr[TN], bvr[TN];
#pragma unroll
    for (int j = 0; j < TN; j++) {
        int c = col0 + tx * TN + j;
        bmr[j] = biasm[c];
        bvr[j] = biasv[c];
    }
#pragma unroll
    for (int i = 0; i < TM; i++) {
        int gr = row0 + ty * TM + i;
        if (gr >= M) continue;
        float isq = g_isq[gr];
        float inv = g_inv[gr];
        float4 om, ov;
        float* omp = reinterpret_cast<float*>(&om);
        float* ovp = reinterpret_cast<float*>(&ov);
#pragma unroll
        for (int j = 0; j < TN; j++) {
            float mean = fmaxf(accm[i][j] + bmr[j], 0.f);
            float var  = fmaxf(accv[i][j] + bvr[j], 0.f);
            float att = expf(-var);
            omp[j] = mean * att * isq;
            ovp[j] = var * att * att * inv;
        }
        *reinterpret_cast<float4*>(&Cm[(size_t)gr * N + col0 + tx * TN]) = om;
        *reinterpret_cast<float4*>(&Cv[(size_t)gr * N + col0 + tx * TN]) = ov;
    }
}

// ---------------- edge aggregation (layer 1: 128 dims) ---------------------
__device__ __forceinline__ void red_v4(float* p, float4 v) {
    asm volatile("red.global.add.v4.f32 [%0], {%1,%2,%3,%4};"
                 :: "l"(p), "f"(v.x), "f"(v.y), "f"(v.z), "f"(v.w)
                 : "memory");
}

__global__ void agg1_kernel(const int* __restrict__ src, const int* __restrict__ dst) {
    int warp = (blockIdx.x * blockDim.x + threadIdx.x) >> 5;
    int lane = threadIdx.x & 31;
    if (warp >= NE) return;
    int s = __ldg(&src[warp]);
    int d = __ldg(&dst[warp]);
    size_t so = (size_t)s * HID + lane * 4;
    size_t dofs = (size_t)d * HID + lane * 4;
    float4 m = *reinterpret_cast<const float4*>(&g_m1[so]);
    red_v4(&g_a1m[dofs], m);
    float4 v = *reinterpret_cast<const float4*>(&g_v1[so]);
    red_v4(&g_a1v[dofs], v);
}

// post-agg for layer 1: h2 = relu(agg * norm) written back into g_m1/g_v1
__global__ void post1_kernel() {
    size_t idx = (size_t)blockIdx.x * blockDim.x + threadIdx.x;
    if (idx >= (size_t)NN * HID) return;
    int i = (int)(idx / HID);
    g_m1[idx] = fmaxf(g_a1m[idx] * g_isq[i], 0.f);
    g_v1[idx] = fmaxf(g_a1v[idx] * g_inv[i], 0.f);
}

// ---------------- edge aggregation (layer 2: 64 dims) ----------------------
__global__ void agg2_kernel(const int* __restrict__ src, const int* __restrict__ dst) {
    int warp = (blockIdx.x * blockDim.x + threadIdx.x) >> 5;
    int lane = threadIdx.x & 31;
    if (warp >= NE) return;
    int s = __ldg(&src[warp]);
    int d = __ldg(&dst[warp]);
    bool isv = lane >= 16;
    int c = (lane & 15) * 4;
    const float* sb = isv ? g_v2 : g_m2;
    float* db = isv ? g_a2v : g_a2m;
    float4 m = *reinterpret_cast<const float4*>(&sb[(size_t)s * OUTF + c]);
    red_v4(&db[(size_t)d * OUTF + c], m);
}

// ---------------- threefry-2x32 (JAX partitionable mode) -------------------
__device__ __forceinline__ uint32_t rotl32(uint32_t x, int r) {
    return __funnelshift_l(x, x, r);
}

__device__ __forceinline__ void threefry_42(uint32_t x0, uint32_t x1,
                                            uint32_t& o0, uint32_t& o1) {
    const uint32_t k0 = 0u, k1 = 42u;
    const uint32_t k2 = k0 ^ k1 ^ 0x1BD11BDAu;
    x0 += k0; x1 += k1;
#define TF_R4(a, b, c, d)                              \
    x0 += x1; x1 = rotl32(x1, a); x1 ^= x0;            \
    x0 += x1; x1 = rotl32(x1, b); x1 ^= x0;            \
    x0 += x1; x1 = rotl32(x1, c); x1 ^= x0;            \
    x0 += x1; x1 = rotl32(x1, d); x1 ^= x0;
    TF_R4(13, 15, 26, 6)  x0 += k1; x1 += k2 + 1u;
    TF_R4(17, 29, 16, 24) x0 += k2; x1 += k0 + 2u;
    TF_R4(13, 15, 26, 6)  x0 += k0; x1 += k1 + 3u;
    TF_R4(17, 29, 16, 24) x0 += k1; x1 += k2 + 4u;
    TF_R4(13, 15, 26, 6)  x0 += k2; x1 += k0 + 5u;
#undef TF_R4
    o0 = x0; o1 = x1;
}

__device__ __forceinline__ float bits_to_normal(uint32_t b) {
    float f = __uint_as_float((b >> 9) | 0x3F800000u) - 1.0f;
    const float LO = -0.99999994f;   // nextafter(-1, 0)
    float u = fmaf(f, 2.0f, LO);
    u = fmaxf(u, LO);
    return 1.41421356f * erfinvf(u);
}

__device__ __forceinline__ float final_val(int f, float eps) {
    int i = f >> 6;  // / OUTF
    float mean = g_a2m[f] * g_isq[i];
    float var = g_a2v[f] * g_inv[i];
    return fmaf(eps, sqrtf(var + 1e-8f), mean);
}

__global__ void final_kernel(float* __restrict__ out) {
    const int total = NN * OUTF;
    int j = blockIdx.x * blockDim.x + threadIdx.x;
    if (j >= total) return;
    uint32_t o0, o1;
    threefry_42(0u, (uint32_t)j, o0, o1);
    uint32_t bits = o0 ^ o1;   // partitionable 32-bit draw
    out[j] = final_val(j, bits_to_normal(bits));
}

// ---------------- launch ----------------------------------------------------
extern "C" void kernel_launch(void* const* d_in, const int* in_sizes, int n_in,
                              void* d_out, int out_size) {
    const float* x   = (const float*)d_in[0];
    const int* src   = (const int*)d_in[1];
    const int* dst   = (const int*)d_in[2];
    const float* wm1 = (const float*)d_in[3];
    const float* wv1 = (const float*)d_in[4];
    const float* bm1 = (const float*)d_in[5];
    const float* bv1 = (const float*)d_in[6];
    const float* wm2 = (const float*)d_in[7];
    const float* wv2 = (const float*)d_in[8];
    const float* bm2 = (const float*)d_in[9];
    const float* bv2 = (const float*)d_in[10];
    float* out = (float*)d_out;

    (void)in_sizes; (void)n_in; (void)out_size;

    float *p_m1, *p_v1, *p_m2, *p_v2;
    cudaGetSymbolAddress((void**)&p_m1, g_m1);
    cudaGetSymbolAddress((void**)&p_v1, g_v1);
    cudaGetSymbolAddress((void**)&p_m2, g_m2);
    cudaGetSymbolAddress((void**)&p_v2, g_v2);

    zero_all_kernel<<<4096, 256>>>();
    deg_kernel<<<(NE + 255) / 256, 256>>>(dst);
    norm_kernel<<<(NN + 255) / 256, 256>>>();

    const int gx = (NN + 127) / 128;

    // layer 1: fused dual GEMM (mean&var share A=x) + msg transform epilogue
    gemm_dual_msg<128, 64, 16, 8, 4, true>
        <<<dim3(gx, HID / 64), 256>>>(x, x, wm1, wv1, bm1, bv1,
                                      p_m1, p_v1, NN, F_IN, HID);

    agg1_kernel<<<NE / 8, 256>>>(src, dst);
    post1_kernel<<<(NN * HID + 255) / 256, 256>>>();

    // layer 2: fused dual GEMM (different A's) + msg transform epilogue
    gemm_dual_msg<128, 64, 16, 8, 4, false>
        <<<dim3(gx, OUTF / 64), 256>>>(p_m1, p_v1, wm2, wv2, bm2, bv2,
                                       p_m2, p_v2, NN, HID, OUTF);

    agg2_kernel<<<NE / 8, 256>>>(src, dst);

    final_kernel<<<(NN * OUTF + 255) / 256, 256>>>(out);
}

// round 4
// speedup vs baseline: 2.1768x; 1.8566x over previous
#include <cuda_runtime.h>
#include <cstdint>

#define NN 100000
#define NE 1600000
#define F_IN 256
#define HID 128
#define OUTF 64
#define NBLK ((NN + 1023) / 1024)   // scan blocks = 98

// ---------------- scratch (device globals; no allocation allowed) ----------
__device__ int   g_cnt[NN];          // in-degree (histogram)
__device__ int   g_ptr[NN];          // CSR row start
__device__ int   g_cursor[NN];       // scatter cursors
__device__ int   g_esrc[NE];         // CSR: src indices grouped by dst
__device__ int   g_bsum[128];        // scan block sums
__device__ float g_isq[NN];          // deg^-1/2
__device__ float g_inv[NN];          // deg^-1
__device__ float g_m1[NN * HID];     // layer-1 messages (mean)
__device__ float g_v1[NN * HID];     // layer-1 messages (var)
__device__ float g_h2m[NN * HID];    // layer-2 inputs (aggregated+relu)
__device__ float g_h2v[NN * HID];
__device__ float g_m2[NN * OUTF];    // layer-2 messages
__device__ float g_v2[NN * OUTF];

// ---------------- CSR build --------------------------------------------------
__global__ void zero_cnt_kernel() {
    int i = blockIdx.x * blockDim.x + threadIdx.x;
    if (i < NN) g_cnt[i] = 0;
}

__global__ void hist_kernel(const int* __restrict__ dst) {
    int e = blockIdx.x * blockDim.x + threadIdx.x;
    if (e < NE) atomicAdd(&g_cnt[dst[e]], 1);
}

// block-local exclusive scan (1024 bins per block) + block sums
__global__ void scan1_kernel() {
    __shared__ int s[1024];
    int t = threadIdx.x;
    int i = blockIdx.x * 1024 + t;
    int v = (i < NN) ? g_cnt[i] : 0;
    s[t] = v;
    __syncthreads();
#pragma unroll
    for (int off = 1; off < 1024; off <<= 1) {
        int x = (t >= off) ? s[t - off] : 0;
        __syncthreads();
        s[t] += x;
        __syncthreads();
    }
    if (i < NN) g_ptr[i] = s[t] - v;      // exclusive, block-local
    if (t == 1023) g_bsum[blockIdx.x] = s[1023];
}

__global__ void scan2_kernel() {
    __shared__ int s[128];
    int t = threadIdx.x;
    s[t] = (t < NBLK) ? g_bsum[t] : 0;
    __syncthreads();
    if (t == 0) {
        int acc = 0;
        for (int b = 0; b < NBLK; b++) { int x = s[b]; s[b] = acc; acc += x; }
    }
    __syncthreads();
    if (t < NBLK) g_bsum[t] = s[t];
}

// finalize ptr/cursor + node norms (deg from histogram)
__global__ void scan3_kernel() {
    int i = blockIdx.x * blockDim.x + threadIdx.x;
    if (i >= NN) return;
    int p = g_ptr[i] + g_bsum[i >> 10];
    g_ptr[i] = p;
    g_cursor[i] = p;
    float d = fmaxf((float)g_cnt[i], 1.0f);
    float is = rsqrtf(d);
    g_isq[i] = is;
    g_inv[i] = is * is;
}

__global__ void scatter_kernel(const int* __restrict__ src,
                               const int* __restrict__ dst) {
    int e = blockIdx.x * blockDim.x + threadIdx.x;
    if (e >= NE) return;
    int d = dst[e];
    int pos = atomicAdd(&g_cursor[d], 1);
    g_esrc[pos] = src[e];
}

// ---------------- cp.async helpers -----------------------------------------
__device__ __forceinline__ void cp_async16(void* smem, const void* gmem) {
    uint32_t s = (uint32_t)__cvta_generic_to_shared(smem);
    asm volatile("cp.async.ca.shared.global [%0], [%1], 16;" :: "r"(s), "l"(gmem));
}
__device__ __forceinline__ void cp_commit() {
    asm volatile("cp.async.commit_group;");
}
__device__ __forceinline__ void cp_wait0() {
    asm volatile("cp.async.wait_group 0;");
}

// ---------------- fused dual GEMM + message-transform epilogue -------------
template <int BM, int BN, int BK, int TM, int TN, bool SAME_A>
__global__ void __launch_bounds__(256, 2)
gemm_dual_msg(const float* __restrict__ Am, const float* __restrict__ Av,
              const float* __restrict__ Wm, const float* __restrict__ Wv,
              const float* __restrict__ biasm, const float* __restrict__ biasv,
              float* __restrict__ Cm, float* __restrict__ Cv,
              int M, int K, int N) {
    constexpr int TX = BN / TN;
    constexpr int TY = BM / TM;
    static_assert(TX * TY == 256, "256 threads");
    static_assert(BK * BN / 4 == 256, "one float4 per thread per B tile");

    __shared__ float Asm[2][BK][BM + 4];
    __shared__ float Asv[SAME_A ? 1 : 2][BK][SAME_A ? 1 : (BM + 4)];
    __shared__ float Bsm[2][BK][BN];
    __shared__ float Bsv[2][BK][BN];

    const int tid = threadIdx.x;
    const int tx = tid % TX;
    const int ty = tid / TX;
    const int row0 = blockIdx.x * BM;
    const int col0 = blockIdx.y * BN;

    constexpr int AROWS = 256 / (BK / 4);
    constexpr int APASS = BM / AROWS;
    const int a_r = tid / (BK / 4);
    const int a_c = (tid % (BK / 4)) * 4;

    const int b_r = tid / (BN / 4);
    const int b_c = (tid % (BN / 4)) * 4;

    float4 pam[APASS], pav[APASS];

    auto fetchA = [&](int k0) {
        const float4 z = make_float4(0.f, 0.f, 0.f, 0.f);
#pragma unroll
        for (int p = 0; p < APASS; p++) {
            int gr = row0 + a_r + p * AROWS;
            pam[p] = (gr < M)
                ? *reinterpret_cast<const float4*>(&Am[(size_t)gr * K + k0 + a_c]) : z;
            if constexpr (!SAME_A)
                pav[p] = (gr < M)
                    ? *reinterpret_cast<const float4*>(&Av[(size_t)gr * K + k0 + a_c]) : z;
        }
    };
    auto stsA = [&](int buf) {
#pragma unroll
        for (int p = 0; p < APASS; p++) {
            int r = a_r + p * AROWS;
            Asm[buf][a_c + 0][r] = pam[p].x;
            Asm[buf][a_c + 1][r] = pam[p].y;
            Asm[buf][a_c + 2][r] = pam[p].z;
            Asm[buf][a_c + 3][r] = pam[p].w;
            if constexpr (!SAME_A) {
                Asv[buf][a_c + 0][r] = pav[p].x;
                Asv[buf][a_c + 1][r] = pav[p].y;
                Asv[buf][a_c + 2][r] = pav[p].z;
                Asv[buf][a_c + 3][r] = pav[p].w;
            }
        }
    };
    auto fetchB = [&](int k0, int buf) {
        cp_async16(&Bsm[buf][b_r][b_c], &Wm[(size_t)(k0 + b_r) * N + col0 + b_c]);
        cp_async16(&Bsv[buf][b_r][b_c], &Wv[(size_t)(k0 + b_r) * N + col0 + b_c]);
        cp_commit();
    };

    float accm[TM][TN], accv[TM][TN];
#pragma unroll
    for (int i = 0; i < TM; i++)
#pragma unroll
        for (int j = 0; j < TN; j++) { accm[i][j] = 0.f; accv[i][j] = 0.f; }

    const int STEPS = K / BK;
    fetchA(0);
    fetchB(0, 0);
    stsA(0);
    cp_wait0();
    __syncthreads();

    int buf = 0;
    for (int s = 0; s < STEPS; s++) {
        if (s + 1 < STEPS) {
            fetchB((s + 1) * BK, buf ^ 1);
            fetchA((s + 1) * BK);
        }
#pragma unroll
        for (int k = 0; k < BK; k++) {
            float arm[TM], arv[TM];
#pragma unroll
            for (int i = 0; i < TM; i += 4)
                *reinterpret_cast<float4*>(&arm[i]) =
                    *reinterpret_cast<const float4*>(&Asm[buf][k][ty * TM + i]);
            if constexpr (!SAME_A) {
#pragma unroll
                for (int i = 0; i < TM; i += 4)
                    *reinterpret_cast<float4*>(&arv[i]) =
                        *reinterpret_cast<const float4*>(&Asv[buf][k][ty * TM + i]);
            }
            float4 bm4 = *reinterpret_cast<const float4*>(&Bsm[buf][k][tx * TN]);
            float4 bv4 = *reinterpret_cast<const float4*>(&Bsv[buf][k][tx * TN]);
            const float* bmp = reinterpret_cast<const float*>(&bm4);
            const float* bvp = reinterpret_cast<const float*>(&bv4);
#pragma unroll
            for (int i = 0; i < TM; i++) {
                float am = arm[i];
                float av = SAME_A ? arm[i] : arv[i];
#pragma unroll
                for (int j = 0; j < TN; j++) {
                    accm[i][j] = fmaf(am, bmp[j], accm[i][j]);
                    accv[i][j] = fmaf(av, bvp[j], accv[i][j]);
                }
            }
        }
        if (s + 1 < STEPS) {
            stsA(buf ^ 1);
            cp_wait0();
            __syncthreads();
            buf ^= 1;
        }
    }

    float bmr[TN], bvr[TN];
#pragma unroll
    for (int j = 0; j < TN; j++) {
        int c = col0 + tx * TN + j;
        bmr[j] = biasm[c];
        bvr[j] = biasv[c];
    }
#pragma unroll
    for (int i = 0; i < TM; i++) {
        int gr = row0 + ty * TM + i;
        if (gr >= M) continue;
        float isq = g_isq[gr];
        float inv = g_inv[gr];
        float4 om, ov;
        float* omp = reinterpret_cast<float*>(&om);
        float* ovp = reinterpret_cast<float*>(&ov);
#pragma unroll
        for (int j = 0; j < TN; j++) {
            float mean = fmaxf(accm[i][j] + bmr[j], 0.f);
            float var  = fmaxf(accv[i][j] + bvr[j], 0.f);
            float att = expf(-var);
            omp[j] = mean * att * isq;
            ovp[j] = var * att * att * inv;
        }
        *reinterpret_cast<float4*>(&Cm[(size_t)gr * N + col0 + tx * TN]) = om;
        *reinterpret_cast<float4*>(&Cv[(size_t)gr * N + col0 + tx * TN]) = ov;
    }
}

// ---------------- layer-1 CSR aggregation + post (relu(sum*norm)) ----------
// one warp per dst node; lane covers 4 dims of mean + 4 dims of var (float4)
__global__ void __launch_bounds__(256)
agg1_csr_kernel() {
    int node = (blockIdx.x * blockDim.x + threadIdx.x) >> 5;
    int lane = threadIdx.x & 31;
    if (node >= NN) return;
    int beg = g_ptr[node];
    int cnt = g_cnt[node];

    const float4* M = reinterpret_cast<const float4*>(g_m1);
    const float4* V = reinterpret_cast<const float4*>(g_v1);

    float4 am = make_float4(0.f, 0.f, 0.f, 0.f);
    float4 av = make_float4(0.f, 0.f, 0.f, 0.f);

    int i = 0;
    for (; i + 2 <= cnt; i += 2) {   // unroll 2 for MLP
        int s0 = __ldg(&g_esrc[beg + i]);
        int s1 = __ldg(&g_esrc[beg + i + 1]);
        float4 m0 = __ldg(&M[(size_t)s0 * (HID / 4) + lane]);
        float4 v0 = __ldg(&V[(size_t)s0 * (HID / 4) + lane]);
        float4 m1 = __ldg(&M[(size_t)s1 * (HID / 4) + lane]);
        float4 v1 = __ldg(&V[(size_t)s1 * (HID / 4) + lane]);
        am.x += m0.x + m1.x; am.y += m0.y + m1.y;
        am.z += m0.z + m1.z; am.w += m0.w + m1.w;
        av.x += v0.x + v1.x; av.y += v0.y + v1.y;
        av.z += v0.z + v1.z; av.w += v0.w + v1.w;
    }
    if (i < cnt) {
        int s0 = __ldg(&g_esrc[beg + i]);
        float4 m0 = __ldg(&M[(size_t)s0 * (HID / 4) + lane]);
        float4 v0 = __ldg(&V[(size_t)s0 * (HID / 4) + lane]);
        am.x += m0.x; am.y += m0.y; am.z += m0.z; am.w += m0.w;
        av.x += v0.x; av.y += v0.y; av.z += v0.z; av.w += v0.w;
    }

    float isq = g_isq[node], inv = g_inv[node];
    float4 om, ov;
    om.x = fmaxf(am.x * isq, 0.f); om.y = fmaxf(am.y * isq, 0.f);
    om.z = fmaxf(am.z * isq, 0.f); om.w = fmaxf(am.w * isq, 0.f);
    ov.x = fmaxf(av.x * inv, 0.f); ov.y = fmaxf(av.y * inv, 0.f);
    ov.z = fmaxf(av.z * inv, 0.f); ov.w = fmaxf(av.w * inv, 0.f);
    reinterpret_cast<float4*>(g_h2m)[(size_t)node * (HID / 4) + lane] = om;
    reinterpret_cast<float4*>(g_h2v)[(size_t)node * (HID / 4) + lane] = ov;
}

// ---------------- threefry-2x32 (JAX partitionable mode) -------------------
__device__ __forceinline__ uint32_t rotl32(uint32_t x, int r) {
    return __funnelshift_l(x, x, r);
}

__device__ __forceinline__ void threefry_42(uint32_t x0, uint32_t x1,
                                            uint32_t& o0, uint32_t& o1) {
    const uint32_t k0 = 0u, k1 = 42u;
    const uint32_t k2 = k0 ^ k1 ^ 0x1BD11BDAu;
    x0 += k0; x1 += k1;
#define TF_R4(a, b, c, d)                              \
    x0 += x1; x1 = rotl32(x1, a); x1 ^= x0;            \
    x0 += x1; x1 = rotl32(x1, b); x1 ^= x0;            \
    x0 += x1; x1 = rotl32(x1, c); x1 ^= x0;            \
    x0 += x1; x1 = rotl32(x1, d); x1 ^= x0;
    TF_R4(13, 15, 26, 6)  x0 += k1; x1 += k2 + 1u;
    TF_R4(17, 29, 16, 24) x0 += k2; x1 += k0 + 2u;
    TF_R4(13, 15, 26, 6)  x0 += k0; x1 += k1 + 3u;
    TF_R4(17, 29, 16, 24) x0 += k1; x1 += k2 + 4u;
    TF_R4(13, 15, 26, 6)  x0 += k2; x1 += k0 + 5u;
#undef TF_R4
    o0 = x0; o1 = x1;
}

__device__ __forceinline__ float bits_to_normal(uint32_t b) {
    float f = __uint_as_float((b >> 9) | 0x3F800000u) - 1.0f;
    const float LO = -0.99999994f;   // nextafter(-1, 0)
    float u = fmaf(f, 2.0f, LO);
    u = fmaxf(u, LO);
    return 1.41421356f * erfinvf(u);
}

// ---------------- layer-2 CSR aggregation + final epilogue -----------------
// one warp per dst node; lane covers dims (2l, 2l+1) of mean and var (float2)
__global__ void __launch_bounds__(256)
agg2_final_kernel(float* __restrict__ out) {
    int node = (blockIdx.x * blockDim.x + threadIdx.x) >> 5;
    int lane = threadIdx.x & 31;
    if (node >= NN) return;
    int beg = g_ptr[node];
    int cnt = g_cnt[node];

    const float2* M = reinterpret_cast<const float2*>(g_m2);
    const float2* V = reinterpret_cast<const float2*>(g_v2);

    float2 am = make_float2(0.f, 0.f);
    float2 av = make_float2(0.f, 0.f);

    int i = 0;
    for (; i + 2 <= cnt; i += 2) {
        int s0 = __ldg(&g_esrc[beg + i]);
        int s1 = __ldg(&g_esrc[beg + i + 1]);
        float2 m0 = __ldg(&M[(size_t)s0 * (OUTF / 2) + lane]);
        float2 v0 = __ldg(&V[(size_t)s0 * (OUTF / 2) + lane]);
        float2 m1 = __ldg(&M[(size_t)s1 * (OUTF / 2) + lane]);
        float2 v1 = __ldg(&V[(size_t)s1 * (OUTF / 2) + lane]);
        am.x += m0.x + m1.x; am.y += m0.y + m1.y;
        av.x += v0.x + v1.x; av.y += v0.y + v1.y;
    }
    if (i < cnt) {
        int s0 = __ldg(&g_esrc[beg + i]);
        float2 m0 = __ldg(&M[(size_t)s0 * (OUTF / 2) + lane]);
        float2 v0 = __ldg(&V[(size_t)s0 * (OUTF / 2) + lane]);
        am.x += m0.x; am.y += m0.y;
        av.x += v0.x; av.y += v0.y;
    }

    float isq = g_isq[node], inv = g_inv[node];
    float mean0 = am.x * isq, mean1 = am.y * isq;
    float var0  = av.x * inv, var1  = av.y * inv;

    int j0 = node * OUTF + 2 * lane;
    uint32_t a0, a1, b0, b1;
    threefry_42(0u, (uint32_t)j0, a0, a1);
    threefry_42(0u, (uint32_t)(j0 + 1), b0, b1);
    float eps0 = bits_to_normal(a0 ^ a1);
    float eps1 = bits_to_normal(b0 ^ b1);

    float2 o;
    o.x = fmaf(eps0, sqrtf(var0 + 1e-8f), mean0);
    o.y = fmaf(eps1, sqrtf(var1 + 1e-8f), mean1);
    reinterpret_cast<float2*>(out)[(size_t)node * (OUTF / 2) + lane] = o;
}

// ---------------- launch ----------------------------------------------------
extern "C" void kernel_launch(void* const* d_in, const int* in_sizes, int n_in,
                              void* d_out, int out_size) {
    const float* x   = (const float*)d_in[0];
    const int* src   = (const int*)d_in[1];
    const int* dst   = (const int*)d_in[2];
    const float* wm1 = (const float*)d_in[3];
    const float* wv1 = (const float*)d_in[4];
    const float* bm1 = (const float*)d_in[5];
    const float* bv1 = (const float*)d_in[6];
    const float* wm2 = (const float*)d_in[7];
    const float* wv2 = (const float*)d_in[8];
    const float* bm2 = (const float*)d_in[9];
    const float* bv2 = (const float*)d_in[10];
    float* out = (float*)d_out;

    (void)in_sizes; (void)n_in; (void)out_size;

    float *p_m1, *p_v1, *p_h2m, *p_h2v, *p_m2, *p_v2;
    cudaGetSymbolAddress((void**)&p_m1, g_m1);
    cudaGetSymbolAddress((void**)&p_v1, g_v1);
    cudaGetSymbolAddress((void**)&p_h2m, g_h2m);
    cudaGetSymbolAddress((void**)&p_h2v, g_h2v);
    cudaGetSymbolAddress((void**)&p_m2, g_m2);
    cudaGetSymbolAddress((void**)&p_v2, g_v2);

    // CSR build + norms
    zero_cnt_kernel<<<(NN + 255) / 256, 256>>>();
    hist_kernel<<<(NE + 255) / 256, 256>>>(dst);
    scan1_kernel<<<NBLK, 1024>>>();
    scan2_kernel<<<1, 128>>>();
    scan3_kernel<<<(NN + 255) / 256, 256>>>();
    scatter_kernel<<<(NE + 255) / 256, 256>>>(src, dst);

    const int gx = (NN + 127) / 128;
    const int agg_blocks = (NN * 32 + 255) / 256;

    // layer 1: fused dual GEMM + msg epilogue
    gemm_dual_msg<128, 64, 16, 8, 4, true>
        <<<dim3(gx, HID / 64), 256>>>(x, x, wm1, wv1, bm1, bv1,
                                      p_m1, p_v1, NN, F_IN, HID);

    // layer 1 aggregation + relu(sum*norm) fused
    agg1_csr_kernel<<<agg_blocks, 256>>>();

    // layer 2: fused dual GEMM + msg epilogue
    gemm_dual_msg<128, 64, 16, 8, 4, false>
        <<<dim3(gx, OUTF / 64), 256>>>(p_h2m, p_h2v, wm2, wv2, bm2, bv2,
                                       p_m2, p_v2, NN, HID, OUTF);

    // layer 2 aggregation + final reparameterized sample fused
    agg2_final_kernel<<<agg_blocks, 256>>>(out);
}

// round 5
// speedup vs baseline: 2.9164x; 1.3398x over previous
#include <cuda_runtime.h>
#include <cstdint>

#define NN 100000
#define NE 1600000
#define F_IN 256
#define HID 128
#define OUTF 64
#define NBLK ((NN + 1023) / 1024)   // scan blocks = 98

// ---------------- scratch (device globals; no allocation allowed) ----------
__device__ int   g_cnt[NN];          // in-degree (histogram)
__device__ int   g_ptr[NN];          // CSR row start
__device__ int   g_cursor[NN];       // scatter cursors
__device__ int   g_esrc[NE];         // CSR: src indices grouped by dst
__device__ int   g_bsum[128];        // scan block sums
__device__ float g_isq[NN];          // deg^-1/2
__device__ float g_inv[NN];          // deg^-1
__device__ float g_m1[NN * HID];     // layer-1 messages (mean)
__device__ float g_v1[NN * HID];     // layer-1 messages (var)
__device__ float g_h2m[NN * HID];    // layer-2 inputs (aggregated+relu)
__device__ float g_h2v[NN * HID];
__device__ float g_m2[NN * OUTF];    // layer-2 messages
__device__ float g_v2[NN * OUTF];

// ---------------- CSR build --------------------------------------------------
__global__ void zero_cnt_kernel() {
    int i = blockIdx.x * blockDim.x + threadIdx.x;
    if (i < NN) g_cnt[i] = 0;
}

__global__ void hist_kernel(const int* __restrict__ dst) {
    int e = blockIdx.x * blockDim.x + threadIdx.x;
    if (e < NE) atomicAdd(&g_cnt[dst[e]], 1);
}

__global__ void scan1_kernel() {
    __shared__ int s[1024];
    int t = threadIdx.x;
    int i = blockIdx.x * 1024 + t;
    int v = (i < NN) ? g_cnt[i] : 0;
    s[t] = v;
    __syncthreads();
#pragma unroll
    for (int off = 1; off < 1024; off <<= 1) {
        int x = (t >= off) ? s[t - off] : 0;
        __syncthreads();
        s[t] += x;
        __syncthreads();
    }
    if (i < NN) g_ptr[i] = s[t] - v;
    if (t == 1023) g_bsum[blockIdx.x] = s[1023];
}

__global__ void scan2_kernel() {
    __shared__ int s[128];
    int t = threadIdx.x;
    s[t] = (t < NBLK) ? g_bsum[t] : 0;
    __syncthreads();
    if (t == 0) {
        int acc = 0;
        for (int b = 0; b < NBLK; b++) { int x = s[b]; s[b] = acc; acc += x; }
    }
    __syncthreads();
    if (t < NBLK) g_bsum[t] = s[t];
}

__global__ void scan3_kernel() {
    int i = blockIdx.x * blockDim.x + threadIdx.x;
    if (i >= NN) return;
    int p = g_ptr[i] + g_bsum[i >> 10];
    g_ptr[i] = p;
    g_cursor[i] = p;
    float d = fmaxf((float)g_cnt[i], 1.0f);
    float is = rsqrtf(d);
    g_isq[i] = is;
    g_inv[i] = is * is;
}

__global__ void scatter_kernel(const int* __restrict__ src,
                               const int* __restrict__ dst) {
    int e = blockIdx.x * blockDim.x + threadIdx.x;
    if (e >= NE) return;
    int d = dst[e];
    int pos = atomicAdd(&g_cursor[d], 1);
    g_esrc[pos] = src[e];
}

// ---------------- tf32 helpers ----------------------------------------------
__device__ __forceinline__ float to_tf32(float x) {
    uint32_t u;
    asm("cvt.rna.tf32.f32 %0, %1;" : "=r"(u) : "f"(x));
    return __uint_as_float(u);
}
__device__ __forceinline__ float4 to_tf32_4(float4 v) {
    v.x = to_tf32(v.x); v.y = to_tf32(v.y);
    v.z = to_tf32(v.z); v.w = to_tf32(v.w);
    return v;
}

__device__ __forceinline__ void mma_tf32(float* d, const uint32_t* a,
                                         uint32_t b0, uint32_t b1) {
    asm volatile(
        "mma.sync.aligned.m16n8k8.row.col.f32.tf32.tf32.f32 "
        "{%0,%1,%2,%3}, {%4,%5,%6,%7}, {%8,%9}, {%0,%1,%2,%3};"
        : "+f"(d[0]), "+f"(d[1]), "+f"(d[2]), "+f"(d[3])
        : "r"(a[0]), "r"(a[1]), "r"(a[2]), "r"(a[3]), "r"(b0), "r"(b1));
}

// ---------------- fused dual GEMM (tf32 tensor cores) + msg epilogue --------
// D_mean = relu(Am@Wm+bm), D_var = relu(Av@Wv+bv); att = exp(-var);
// Cm = mean*att*isq[row], Cv = var*att^2*inv[row].
// BM=128, BN=64, 8 warps as 4(M)x2(N), warp tile 32x32 per matrix.
template <int BK, bool SAME_A>
__global__ void __launch_bounds__(256)
gemm_dual_mma(const float* __restrict__ Am, const float* __restrict__ Av,
              const float* __restrict__ Wm, const float* __restrict__ Wv,
              const float* __restrict__ biasm, const float* __restrict__ biasv,
              float* __restrict__ Cm, float* __restrict__ Cv,
              int M, int K, int N) {
    constexpr int BM = 128;
    constexpr int BN = 64;
    constexpr int AP = BK + 4;    // A row stride (floats): conflict-free + 16B
    constexpr int BP = 72;        // B row stride
    constexpr int KSTEPS = BK / 8;

    __shared__ float Asm[2][BM][AP];
    __shared__ float Asv[SAME_A ? 1 : 2][SAME_A ? 1 : BM][SAME_A ? 1 : AP];
    __shared__ float Bsm[2][BK][BP];
    __shared__ float Bsv[2][BK][BP];

    const int tid = threadIdx.x;
    const int warp = tid >> 5;
    const int lane = tid & 31;
    const int g = lane >> 2;       // group id (0..7)
    const int c = lane & 3;        // thread-in-group
    const int wm = warp & 3;       // warp M index (0..3)
    const int wn = warp >> 2;      // warp N index (0..1)
    const int wmBase = wm * 32;
    const int wnBase = wn * 32;

    const int col0 = blockIdx.x * BN;
    const int row0 = blockIdx.y * BM;

    // A loader geometry
    constexpr int TPR = BK / 4;          // threads per A row
    constexpr int AROWS = 256 / TPR;
    constexpr int APASS = BM / AROWS;
    const int a_r = tid / TPR;
    const int a_c = (tid % TPR) * 4;

    // B loader geometry (BK*16 float4s)
    const int b_r = tid / 16;
    const int b_c = (tid % 16) * 4;
    const bool b_act = tid < BK * 16;

    float4 pam[APASS], pav[APASS], pbm, pbv;

    auto fetch = [&](int k0) {
        const float4 z = make_float4(0.f, 0.f, 0.f, 0.f);
#pragma unroll
        for (int p = 0; p < APASS; p++) {
            int gr = row0 + a_r + p * AROWS;
            pam[p] = (gr < M)
                ? *reinterpret_cast<const float4*>(&Am[(size_t)gr * K + k0 + a_c]) : z;
            if constexpr (!SAME_A)
                pav[p] = (gr < M)
                    ? *reinterpret_cast<const float4*>(&Av[(size_t)gr * K + k0 + a_c]) : z;
        }
        if (b_act) {
            pbm = *reinterpret_cast<const float4*>(&Wm[(size_t)(k0 + b_r) * N + col0 + b_c]);
            pbv = *reinterpret_cast<const float4*>(&Wv[(size_t)(k0 + b_r) * N + col0 + b_c]);
        }
    };
    auto sts = [&](int buf) {
#pragma unroll
        for (int p = 0; p < APASS; p++) {
            int r = a_r + p * AROWS;
            *reinterpret_cast<float4*>(&Asm[buf][r][a_c]) = to_tf32_4(pam[p]);
            if constexpr (!SAME_A)
                *reinterpret_cast<float4*>(&Asv[buf][r][a_c]) = to_tf32_4(pav[p]);
        }
        if (b_act) {
            *reinterpret_cast<float4*>(&Bsm[buf][b_r][b_c]) = to_tf32_4(pbm);
            *reinterpret_cast<float4*>(&Bsv[buf][b_r][b_c]) = to_tf32_4(pbv);
        }
    };

    float dm[2][4][4], dv[2][4][4];
#pragma unroll
    for (int mt = 0; mt < 2; mt++)
#pragma unroll
        for (int nt = 0; nt < 4; nt++)
#pragma unroll
            for (int r = 0; r < 4; r++) { dm[mt][nt][r] = 0.f; dv[mt][nt][r] = 0.f; }

    const int STEPS = K / BK;
    fetch(0);
    sts(0);
    __syncthreads();

    int buf = 0;
    for (int s = 0; s < STEPS; s++) {
        if (s + 1 < STEPS) fetch((s + 1) * BK);
#pragma unroll
        for (int kk = 0; kk < KSTEPS; kk++) {
            const int k0 = kk * 8;
            uint32_t am[2][4], av[2][4];
#pragma unroll
            for (int mt = 0; mt < 2; mt++) {
                int m0 = wmBase + mt * 16;
                am[mt][0] = __float_as_uint(Asm[buf][m0 + g][k0 + c]);
                am[mt][1] = __float_as_uint(Asm[buf][m0 + g + 8][k0 + c]);
                am[mt][2] = __float_as_uint(Asm[buf][m0 + g][k0 + c + 4]);
                am[mt][3] = __float_as_uint(Asm[buf][m0 + g + 8][k0 + c + 4]);
                if constexpr (!SAME_A) {
                    av[mt][0] = __float_as_uint(Asv[buf][m0 + g][k0 + c]);
                    av[mt][1] = __float_as_uint(Asv[buf][m0 + g + 8][k0 + c]);
                    av[mt][2] = __float_as_uint(Asv[buf][m0 + g][k0 + c + 4]);
                    av[mt][3] = __float_as_uint(Asv[buf][m0 + g + 8][k0 + c + 4]);
                }
            }
#pragma unroll
            for (int nt = 0; nt < 4; nt++) {
                int n0 = wnBase + nt * 8 + g;
                uint32_t bm0 = __float_as_uint(Bsm[buf][k0 + c][n0]);
                uint32_t bm1 = __float_as_uint(Bsm[buf][k0 + c + 4][n0]);
                uint32_t bv0 = __float_as_uint(Bsv[buf][k0 + c][n0]);
                uint32_t bv1 = __float_as_uint(Bsv[buf][k0 + c + 4][n0]);
#pragma unroll
                for (int mt = 0; mt < 2; mt++) {
                    mma_tf32(dm[mt][nt], am[mt], bm0, bm1);
                    if constexpr (SAME_A)
                        mma_tf32(dv[mt][nt], am[mt], bv0, bv1);
                    else
                        mma_tf32(dv[mt][nt], av[mt], bv0, bv1);
                }
            }
        }
        if (s + 1 < STEPS) {
            __syncthreads();      // all reads of buf^1 from prior iter done
            sts(buf ^ 1);
            __syncthreads();
            buf ^= 1;
        }
    }

    // epilogue: bias + relu + attention + src-norm prescale, float2 stores
#pragma unroll
    for (int nt = 0; nt < 4; nt++) {
        int col = col0 + wnBase + nt * 8 + 2 * c;
        float2 bm2 = *reinterpret_cast<const float2*>(&biasm[col]);
        float2 bv2 = *reinterpret_cast<const float2*>(&biasv[col]);
#pragma unroll
        for (int mt = 0; mt < 2; mt++) {
            int r0 = row0 + wmBase + mt * 16 + g;
#pragma unroll
            for (int h = 0; h < 2; h++) {          // h=0: rows g, h=1: rows g+8
                int r = r0 + h * 8;
                if (r >= M) continue;
                float isq = g_isq[r];
                float inv = g_inv[r];
                float mean0 = fmaxf(dm[mt][nt][2 * h + 0] + bm2.x, 0.f);
                float mean1 = fmaxf(dm[mt][nt][2 * h + 1] + bm2.y, 0.f);
                float var0  = fmaxf(dv[mt][nt][2 * h + 0] + bv2.x, 0.f);
                float var1  = fmaxf(dv[mt][nt][2 * h + 1] + bv2.y, 0.f);
                float att0 = expf(-var0);
                float att1 = expf(-var1);
                float2 om = make_float2(mean0 * att0 * isq, mean1 * att1 * isq);
                float2 ov = make_float2(var0 * att0 * att0 * inv,
                                        var1 * att1 * att1 * inv);
                *reinterpret_cast<float2*>(&Cm[(size_t)r * N + col]) = om;
                *reinterpret_cast<float2*>(&Cv[(size_t)r * N + col]) = ov;
            }
        }
    }
}

// ---------------- layer-1 CSR aggregation + post (relu(sum*norm)) ----------
__global__ void __launch_bounds__(256)
agg1_csr_kernel() {
    int node = (blockIdx.x * blockDim.x + threadIdx.x) >> 5;
    int lane = threadIdx.x & 31;
    if (node >= NN) return;
    int beg = g_ptr[node];
    int cnt = g_cnt[node];

    const float4* M = reinterpret_cast<const float4*>(g_m1);
    const float4* V = reinterpret_cast<const float4*>(g_v1);

    float4 am = make_float4(0.f, 0.f, 0.f, 0.f);
    float4 av = make_float4(0.f, 0.f, 0.f, 0.f);

    int i = 0;
    for (; i + 2 <= cnt; i += 2) {
        int s0 = __ldg(&g_esrc[beg + i]);
        int s1 = __ldg(&g_esrc[beg + i + 1]);
        float4 m0 = __ldg(&M[(size_t)s0 * (HID / 4) + lane]);
        float4 v0 = __ldg(&V[(size_t)s0 * (HID / 4) + lane]);
        float4 m1 = __ldg(&M[(size_t)s1 * (HID / 4) + lane]);
        float4 v1 = __ldg(&V[(size_t)s1 * (HID / 4) + lane]);
        am.x += m0.x + m1.x; am.y += m0.y + m1.y;
        am.z += m0.z + m1.z; am.w += m0.w + m1.w;
        av.x += v0.x + v1.x; av.y += v0.y + v1.y;
        av.z += v0.z + v1.z; av.w += v0.w + v1.w;
    }
    if (i < cnt) {
        int s0 = __ldg(&g_esrc[beg + i]);
        float4 m0 = __ldg(&M[(size_t)s0 * (HID / 4) + lane]);
        float4 v0 = __ldg(&V[(size_t)s0 * (HID / 4) + lane]);
        am.x += m0.x; am.y += m0.y; am.z += m0.z; am.w += m0.w;
        av.x += v0.x; av.y += v0.y; av.z += v0.z; av.w += v0.w;
    }

    float isq = g_isq[node], inv = g_inv[node];
    float4 om, ov;
    om.x = fmaxf(am.x * isq, 0.f); om.y = fmaxf(am.y * isq, 0.f);
    om.z = fmaxf(am.z * isq, 0.f); om.w = fmaxf(am.w * isq, 0.f);
    ov.x = fmaxf(av.x * inv, 0.f); ov.y = fmaxf(av.y * inv, 0.f);
    ov.z = fmaxf(av.z * inv, 0.f); ov.w = fmaxf(av.w * inv, 0.f);
    reinterpret_cast<float4*>(g_h2m)[(size_t)node * (HID / 4) + lane] = om;
    reinterpret_cast<float4*>(g_h2v)[(size_t)node * (HID / 4) + lane] = ov;
}

// ---------------- threefry-2x32 (JAX partitionable mode) -------------------
__device__ __forceinline__ uint32_t rotl32(uint32_t x, int r) {
    return __funnelshift_l(x, x, r);
}

__device__ __forceinline__ void threefry_42(uint32_t x0, uint32_t x1,
                                            uint32_t& o0, uint32_t& o1) {
    const uint32_t k0 = 0u, k1 = 42u;
    const uint32_t k2 = k0 ^ k1 ^ 0x1BD11BDAu;
    x0 += k0; x1 += k1;
#define TF_R4(a, b, c, d)                              \
    x0 += x1; x1 = rotl32(x1, a); x1 ^= x0;            \
    x0 += x1; x1 = rotl32(x1, b); x1 ^= x0;            \
    x0 += x1; x1 = rotl32(x1, c); x1 ^= x0;            \
    x0 += x1; x1 = rotl32(x1, d); x1 ^= x0;
    TF_R4(13, 15, 26, 6)  x0 += k1; x1 += k2 + 1u;
    TF_R4(17, 29, 16, 24) x0 += k2; x1 += k0 + 2u;
    TF_R4(13, 15, 26, 6)  x0 += k0; x1 += k1 + 3u;
    TF_R4(17, 29, 16, 24) x0 += k1; x1 += k2 + 4u;
    TF_R4(13, 15, 26, 6)  x0 += k2; x1 += k0 + 5u;
#undef TF_R4
    o0 = x0; o1 = x1;
}

__device__ __forceinline__ float bits_to_normal(uint32_t b) {
    float f = __uint_as_float((b >> 9) | 0x3F800000u) - 1.0f;
    const float LO = -0.99999994f;   // nextafter(-1, 0)
    float u = fmaf(f, 2.0f, LO);
    u = fmaxf(u, LO);
    return 1.41421356f * erfinvf(u);
}

// ---------------- layer-2 CSR aggregation + final epilogue -----------------
__global__ void __launch_bounds__(256)
agg2_final_kernel(float* __restrict__ out) {
    int node = (blockIdx.x * blockDim.x + threadIdx.x) >> 5;
    int lane = threadIdx.x & 31;
    if (node >= NN) return;
    int beg = g_ptr[node];
    int cnt = g_cnt[node];

    const float2* M = reinterpret_cast<const float2*>(g_m2);
    const float2* V = reinterpret_cast<const float2*>(g_v2);

    float2 am = make_float2(0.f, 0.f);
    float2 av = make_float2(0.f, 0.f);

    int i = 0;
    for (; i + 2 <= cnt; i += 2) {
        int s0 = __ldg(&g_esrc[beg + i]);
        int s1 = __ldg(&g_esrc[beg + i + 1]);
        float2 m0 = __ldg(&M[(size_t)s0 * (OUTF / 2) + lane]);
        float2 v0 = __ldg(&V[(size_t)s0 * (OUTF / 2) + lane]);
        float2 m1 = __ldg(&M[(size_t)s1 * (OUTF / 2) + lane]);
        float2 v1 = __ldg(&V[(size_t)s1 * (OUTF / 2) + lane]);
        am.x += m0.x + m1.x; am.y += m0.y + m1.y;
        av.x += v0.x + v1.x; av.y += v0.y + v1.y;
    }
    if (i < cnt) {
        int s0 = __ldg(&g_esrc[beg + i]);
        float2 m0 = __ldg(&M[(size_t)s0 * (OUTF / 2) + lane]);
        float2 v0 = __ldg(&V[(size_t)s0 * (OUTF / 2) + lane]);
        am.x += m0.x; am.y += m0.y;
        av.x += v0.x; av.y += v0.y;
    }

    float isq = g_isq[node], inv = g_inv[node];
    float mean0 = am.x * isq, mean1 = am.y * isq;
    float var0  = av.x * inv, var1  = av.y * inv;

    int j0 = node * OUTF + 2 * lane;
    uint32_t a0, a1, b0, b1;
    threefry_42(0u, (uint32_t)j0, a0, a1);
    threefry_42(0u, (uint32_t)(j0 + 1), b0, b1);
    float eps0 = bits_to_normal(a0 ^ a1);
    float eps1 = bits_to_normal(b0 ^ b1);

    float2 o;
    o.x = fmaf(eps0, sqrtf(var0 + 1e-8f), mean0);
    o.y = fmaf(eps1, sqrtf(var1 + 1e-8f), mean1);
    reinterpret_cast<float2*>(out)[(size_t)node * (OUTF / 2) + lane] = o;
}

// ---------------- launch ----------------------------------------------------
extern "C" void kernel_launch(void* const* d_in, const int* in_sizes, int n_in,
                              void* d_out, int out_size) {
    const float* x   = (const float*)d_in[0];
    const int* src   = (const int*)d_in[1];
    const int* dst   = (const int*)d_in[2];
    const float* wm1 = (const float*)d_in[3];
    const float* wv1 = (const float*)d_in[4];
    const float* bm1 = (const float*)d_in[5];
    const float* bv1 = (const float*)d_in[6];
    const float* wm2 = (const float*)d_in[7];
    const float* wv2 = (const float*)d_in[8];
    const float* bm2 = (const float*)d_in[9];
    const float* bv2 = (const float*)d_in[10];
    float* out = (float*)d_out;

    (void)in_sizes; (void)n_in; (void)out_size;

    float *p_h2m, *p_h2v, *p_m1, *p_v1, *p_m2, *p_v2;
    cudaGetSymbolAddress((void**)&p_m1, g_m1);
    cudaGetSymbolAddress((void**)&p_v1, g_v1);
    cudaGetSymbolAddress((void**)&p_h2m, g_h2m);
    cudaGetSymbolAddress((void**)&p_h2v, g_h2v);
    cudaGetSymbolAddress((void**)&p_m2, g_m2);
    cudaGetSymbolAddress((void**)&p_v2, g_v2);

    // CSR build + norms
    zero_cnt_kernel<<<(NN + 255) / 256, 256>>>();
    hist_kernel<<<(NE + 255) / 256, 256>>>(dst);
    scan1_kernel<<<NBLK, 1024>>>();
    scan2_kernel<<<1, 128>>>();
    scan3_kernel<<<(NN + 255) / 256, 256>>>();
    scatter_kernel<<<(NE + 255) / 256, 256>>>(src, dst);

    const int gridM = (NN + 127) / 128;
    const int agg_blocks = (NN * 32 + 255) / 256;

    // layer 1: tf32 mma dual GEMM + msg epilogue (N-block fastest for L2 reuse)
    gemm_dual_mma<16, true>
        <<<dim3(HID / 64, gridM), 256>>>(x, x, wm1, wv1, bm1, bv1,
                                         p_m1, p_v1, NN, F_IN, HID);

    agg1_csr_kernel<<<agg_blocks, 256>>>();

    // layer 2: tf32 mma dual GEMM (separate A's) + msg epilogue
    gemm_dual_mma<8, false>
        <<<dim3(OUTF / 64, gridM), 256>>>(p_h2m, p_h2v, wm2, wv2, bm2, bv2,
                                          p_m2, p_v2, NN, HID, OUTF);

    agg2_final_kernel<<<agg_blocks, 256>>>(out);
}

// round 6
// speedup vs baseline: 3.2112x; 1.1011x over previous
#include <cuda_runtime.h>
#include <cstdint>

#define NN 100000
#define NE 1600000
#define F_IN 256
#define HID 128
#define OUTF 64
#define NBLK ((NN + 1023) / 1024)   // scan blocks = 98

// ---------------- scratch (device globals; no allocation allowed) ----------
__device__ int   g_cnt[NN];          // in-degree (histogram)
__device__ int   g_ptr[NN];          // CSR row start
__device__ int   g_cursor[NN];       // scatter cursors
__device__ int   g_esrc[NE];         // CSR: src indices grouped by dst
__device__ int   g_bsum[128];        // scan block sums
__device__ float g_isq[NN];          // deg^-1/2
__device__ float g_inv[NN];          // deg^-1
__device__ float g_m1[NN * HID];     // layer-1 messages (mean*att), no norm
__device__ float g_v1[NN * HID];     // layer-1 messages (var*att^2), no norm
__device__ float g_h2m[NN * HID];    // layer-2 inputs (aggregated+relu)
__device__ float g_h2v[NN * HID];
__device__ float g_m2[NN * OUTF];    // layer-2 messages (norm-prescaled)
__device__ float g_v2[NN * OUTF];

// ---------------- CSR build --------------------------------------------------
__global__ void zero_cnt_kernel() {
    int i = blockIdx.x * blockDim.x + threadIdx.x;
    if (i < NN) g_cnt[i] = 0;
}

__global__ void hist_kernel(const int* __restrict__ dst) {
    int e = blockIdx.x * blockDim.x + threadIdx.x;
    if (e < NE) atomicAdd(&g_cnt[dst[e]], 1);
}

__global__ void scan1_kernel() {
    __shared__ int s[1024];
    int t = threadIdx.x;
    int i = blockIdx.x * 1024 + t;
    int v = (i < NN) ? g_cnt[i] : 0;
    s[t] = v;
    __syncthreads();
#pragma unroll
    for (int off = 1; off < 1024; off <<= 1) {
        int x = (t >= off) ? s[t - off] : 0;
        __syncthreads();
        s[t] += x;
        __syncthreads();
    }
    if (i < NN) g_ptr[i] = s[t] - v;
    if (t == 1023) g_bsum[blockIdx.x] = s[1023];
}

__global__ void scan2_kernel() {
    __shared__ int s[128];
    int t = threadIdx.x;
    s[t] = (t < NBLK) ? g_bsum[t] : 0;
    __syncthreads();
    if (t == 0) {
        int acc = 0;
        for (int b = 0; b < NBLK; b++) { int x = s[b]; s[b] = acc; acc += x; }
    }
    __syncthreads();
    if (t < NBLK) g_bsum[t] = s[t];
}

__global__ void scan3_kernel() {
    int i = blockIdx.x * blockDim.x + threadIdx.x;
    if (i >= NN) return;
    int p = g_ptr[i] + g_bsum[i >> 10];
    g_ptr[i] = p;
    g_cursor[i] = p;
    float d = fmaxf((float)g_cnt[i], 1.0f);
    float is = rsqrtf(d);
    g_isq[i] = is;
    g_inv[i] = is * is;
}

__global__ void scatter_kernel(const int* __restrict__ src,
                               const int* __restrict__ dst) {
    int e = blockIdx.x * blockDim.x + threadIdx.x;
    if (e >= NE) return;
    int d = dst[e];
    int pos = atomicAdd(&g_cursor[d], 1);
    g_esrc[pos] = src[e];
}

// ---------------- tf32 helpers ----------------------------------------------
__device__ __forceinline__ float to_tf32(float x) {
    uint32_t u;
    asm("cvt.rna.tf32.f32 %0, %1;" : "=r"(u) : "f"(x));
    return __uint_as_float(u);
}
__device__ __forceinline__ float4 to_tf32_4(float4 v) {
    v.x = to_tf32(v.x); v.y = to_tf32(v.y);
    v.z = to_tf32(v.z); v.w = to_tf32(v.w);
    return v;
}

__device__ __forceinline__ void mma_tf32(float* d, const uint32_t* a,
                                         uint32_t b0, uint32_t b1) {
    asm volatile(
        "mma.sync.aligned.m16n8k8.row.col.f32.tf32.tf32.f32 "
        "{%0,%1,%2,%3}, {%4,%5,%6,%7}, {%8,%9}, {%0,%1,%2,%3};"
        : "+f"(d[0]), "+f"(d[1]), "+f"(d[2]), "+f"(d[3])
        : "r"(a[0]), "r"(a[1]), "r"(a[2]), "r"(a[3]), "r"(b0), "r"(b1));
}

// ---------------- fused dual GEMM (tf32) + msg epilogue ---------------------
// mean = relu(Am@Wm+bm), var = relu(Av@Wv+bv); att = exp(-var);
// NORM=true : Cm = mean*att*isq[row], Cv = var*att^2*inv[row]  (layer 2)
// NORM=false: Cm = mean*att,          Cv = var*att^2           (layer 1;
//             src-norm applied during aggregation instead)
template <int BK, bool SAME_A, bool NORM>
__global__ void __launch_bounds__(256)
gemm_dual_mma(const float* __restrict__ Am, const float* __restrict__ Av,
              const float* __restrict__ Wm, const float* __restrict__ Wv,
              const float* __restrict__ biasm, const float* __restrict__ biasv,
              float* __restrict__ Cm, float* __restrict__ Cv,
              int M, int K, int N) {
    constexpr int BM = 128;
    constexpr int BN = 64;
    constexpr int AP = BK + 4;
    constexpr int BP = 72;
    constexpr int KSTEPS = BK / 8;

    __shared__ float Asm[2][BM][AP];
    __shared__ float Asv[SAME_A ? 1 : 2][SAME_A ? 1 : BM][SAME_A ? 1 : AP];
    __shared__ float Bsm[2][BK][BP];
    __shared__ float Bsv[2][BK][BP];

    const int tid = threadIdx.x;
    const int warp = tid >> 5;
    const int lane = tid & 31;
    const int g = lane >> 2;
    const int c = lane & 3;
    const int wm = warp & 3;
    const int wn = warp >> 2;
    const int wmBase = wm * 32;
    const int wnBase = wn * 32;

    const int col0 = blockIdx.x * BN;
    const int row0 = blockIdx.y * BM;

    constexpr int TPR = BK / 4;
    constexpr int AROWS = 256 / TPR;
    constexpr int APASS = BM / AROWS;
    const int a_r = tid / TPR;
    const int a_c = (tid % TPR) * 4;

    const int b_r = tid / 16;
    const int b_c = (tid % 16) * 4;
    const bool b_act = tid < BK * 16;

    float4 pam[APASS], pav[APASS], pbm, pbv;

    auto fetch = [&](int k0) {
        const float4 z = make_float4(0.f, 0.f, 0.f, 0.f);
#pragma unroll
        for (int p = 0; p < APASS; p++) {
            int gr = row0 + a_r + p * AROWS;
            pam[p] = (gr < M)
                ? *reinterpret_cast<const float4*>(&Am[(size_t)gr * K + k0 + a_c]) : z;
            if constexpr (!SAME_A)
                pav[p] = (gr < M)
                    ? *reinterpret_cast<const float4*>(&Av[(size_t)gr * K + k0 + a_c]) : z;
        }
        if (b_act) {
            pbm = *reinterpret_cast<const float4*>(&Wm[(size_t)(k0 + b_r) * N + col0 + b_c]);
            pbv = *reinterpret_cast<const float4*>(&Wv[(size_t)(k0 + b_r) * N + col0 + b_c]);
        }
    };
    auto sts = [&](int buf) {
#pragma unroll
        for (int p = 0; p < APASS; p++) {
            int r = a_r + p * AROWS;
            *reinterpret_cast<float4*>(&Asm[buf][r][a_c]) = to_tf32_4(pam[p]);
            if constexpr (!SAME_A)
                *reinterpret_cast<float4*>(&Asv[buf][r][a_c]) = to_tf32_4(pav[p]);
        }
        if (b_act) {
            *reinterpret_cast<float4*>(&Bsm[buf][b_r][b_c]) = to_tf32_4(pbm);
            *reinterpret_cast<float4*>(&Bsv[buf][b_r][b_c]) = to_tf32_4(pbv);
        }
    };

    float dm[2][4][4], dv[2][4][4];
#pragma unroll
    for (int mt = 0; mt < 2; mt++)
#pragma unroll
        for (int nt = 0; nt < 4; nt++)
#pragma unroll
            for (int r = 0; r < 4; r++) { dm[mt][nt][r] = 0.f; dv[mt][nt][r] = 0.f; }

    const int STEPS = K / BK;
    fetch(0);
    sts(0);
    __syncthreads();

    int buf = 0;
    for (int s = 0; s < STEPS; s++) {
        if (s + 1 < STEPS) fetch((s + 1) * BK);
#pragma unroll
        for (int kk = 0; kk < KSTEPS; kk++) {
            const int k0 = kk * 8;
            uint32_t am[2][4], av[2][4];
#pragma unroll
            for (int mt = 0; mt < 2; mt++) {
                int m0 = wmBase + mt * 16;
                am[mt][0] = __float_as_uint(Asm[buf][m0 + g][k0 + c]);
                am[mt][1] = __float_as_uint(Asm[buf][m0 + g + 8][k0 + c]);
                am[mt][2] = __float_as_uint(Asm[buf][m0 + g][k0 + c + 4]);
                am[mt][3] = __float_as_uint(Asm[buf][m0 + g + 8][k0 + c + 4]);
                if constexpr (!SAME_A) {
                    av[mt][0] = __float_as_uint(Asv[buf][m0 + g][k0 + c]);
                    av[mt][1] = __float_as_uint(Asv[buf][m0 + g + 8][k0 + c]);
                    av[mt][2] = __float_as_uint(Asv[buf][m0 + g][k0 + c + 4]);
                    av[mt][3] = __float_as_uint(Asv[buf][m0 + g + 8][k0 + c + 4]);
                }
            }
#pragma unroll
            for (int nt = 0; nt < 4; nt++) {
                int n0 = wnBase + nt * 8 + g;
                uint32_t bm0 = __float_as_uint(Bsm[buf][k0 + c][n0]);
                uint32_t bm1 = __float_as_uint(Bsm[buf][k0 + c + 4][n0]);
                uint32_t bv0 = __float_as_uint(Bsv[buf][k0 + c][n0]);
                uint32_t bv1 = __float_as_uint(Bsv[buf][k0 + c + 4][n0]);
#pragma unroll
                for (int mt = 0; mt < 2; mt++) {
                    mma_tf32(dm[mt][nt], am[mt], bm0, bm1);
                    if constexpr (SAME_A)
                        mma_tf32(dv[mt][nt], am[mt], bv0, bv1);
                    else
                        mma_tf32(dv[mt][nt], av[mt], bv0, bv1);
                }
            }
        }
        // single sync per step: sts targets buf^1, whose readers finished
        // before the previous sync; readers of buf are all in this iteration.
        if (s + 1 < STEPS) {
            sts(buf ^ 1);
            __syncthreads();
            buf ^= 1;
        }
    }

    // epilogue
#pragma unroll
    for (int nt = 0; nt < 4; nt++) {
        int col = col0 + wnBase + nt * 8 + 2 * c;
        float2 bm2 = *reinterpret_cast<const float2*>(&biasm[col]);
        float2 bv2 = *reinterpret_cast<const float2*>(&biasv[col]);
#pragma unroll
        for (int mt = 0; mt < 2; mt++) {
            int r0 = row0 + wmBase + mt * 16 + g;
#pragma unroll
            for (int h = 0; h < 2; h++) {
                int r = r0 + h * 8;
                if (r >= M) continue;
                float isq = NORM ? g_isq[r] : 1.0f;
                float inv = NORM ? g_inv[r] : 1.0f;
                float mean0 = fmaxf(dm[mt][nt][2 * h + 0] + bm2.x, 0.f);
                float mean1 = fmaxf(dm[mt][nt][2 * h + 1] + bm2.y, 0.f);
                float var0  = fmaxf(dv[mt][nt][2 * h + 0] + bv2.x, 0.f);
                float var1  = fmaxf(dv[mt][nt][2 * h + 1] + bv2.y, 0.f);
                float att0 = expf(-var0);
                float att1 = expf(-var1);
                float2 om, ov;
                if (NORM) {
                    om = make_float2(mean0 * att0 * isq, mean1 * att1 * isq);
                    ov = make_float2(var0 * att0 * att0 * inv,
                                     var1 * att1 * att1 * inv);
                } else {
                    om = make_float2(mean0 * att0, mean1 * att1);
                    ov = make_float2(var0 * att0 * att0, var1 * att1 * att1);
                }
                *reinterpret_cast<float2*>(&Cm[(size_t)r * N + col]) = om;
                *reinterpret_cast<float2*>(&Cv[(size_t)r * N + col]) = ov;
            }
        }
    }
}

// ---------------- layer-1 CSR aggregation (split passes) -------------------
// one warp per dst node, one pass for mean, one for var. Gathered rows are
// scaled by the SRC node norm here (moved out of GEMM1's epilogue so GEMM1
// has no dependency on the CSR/norm chain). Output = relu(sum * dst_norm),
// written with .cs (evict-first) to protect gather residency in L2.
__device__ __forceinline__ void stcs4(float4* p, float4 v) {
    asm volatile("st.global.cs.v4.f32 [%0], {%1,%2,%3,%4};"
                 :: "l"(p), "f"(v.x), "f"(v.y), "f"(v.z), "f"(v.w) : "memory");
}

template <bool ISVAR>
__global__ void __launch_bounds__(256)
agg1_pass_kernel() {
    int node = (blockIdx.x * blockDim.x + threadIdx.x) >> 5;
    int lane = threadIdx.x & 31;
    if (node >= NN) return;
    int beg = g_ptr[node];
    int cnt = g_cnt[node];

    const float4* F = reinterpret_cast<const float4*>(ISVAR ? g_v1 : g_m1);
    const float* SN = ISVAR ? g_inv : g_isq;

    float4 acc = make_float4(0.f, 0.f, 0.f, 0.f);

    int i = 0;
    for (; i + 4 <= cnt; i += 4) {
        int s0 = __ldg(&g_esrc[beg + i]);
        int s1 = __ldg(&g_esrc[beg + i + 1]);
        int s2 = __ldg(&g_esrc[beg + i + 2]);
        int s3 = __ldg(&g_esrc[beg + i + 3]);
        float n0 = __ldg(&SN[s0]);
        float n1 = __ldg(&SN[s1]);
        float n2 = __ldg(&SN[s2]);
        float n3 = __ldg(&SN[s3]);
        float4 f0 = __ldg(&F[(size_t)s0 * (HID / 4) + lane]);
        float4 f1 = __ldg(&F[(size_t)s1 * (HID / 4) + lane]);
        float4 f2 = __ldg(&F[(size_t)s2 * (HID / 4) + lane]);
        float4 f3 = __ldg(&F[(size_t)s3 * (HID / 4) + lane]);
        acc.x = fmaf(f0.x, n0, acc.x); acc.y = fmaf(f0.y, n0, acc.y);
        acc.z = fmaf(f0.z, n0, acc.z); acc.w = fmaf(f0.w, n0, acc.w);
        acc.x = fmaf(f1.x, n1, acc.x); acc.y = fmaf(f1.y, n1, acc.y);
        acc.z = fmaf(f1.z, n1, acc.z); acc.w = fmaf(f1.w, n1, acc.w);
        acc.x = fmaf(f2.x, n2, acc.x); acc.y = fmaf(f2.y, n2, acc.y);
        acc.z = fmaf(f2.z, n2, acc.z); acc.w = fmaf(f2.w, n2, acc.w);
        acc.x = fmaf(f3.x, n3, acc.x); acc.y = fmaf(f3.y, n3, acc.y);
        acc.z = fmaf(f3.z, n3, acc.z); acc.w = fmaf(f3.w, n3, acc.w);
    }
    for (; i < cnt; i++) {
        int s0 = __ldg(&g_esrc[beg + i]);
        float n0 = __ldg(&SN[s0]);
        float4 f0 = __ldg(&F[(size_t)s0 * (HID / 4) + lane]);
        acc.x = fmaf(f0.x, n0, acc.x); acc.y = fmaf(f0.y, n0, acc.y);
        acc.z = fmaf(f0.z, n0, acc.z); acc.w = fmaf(f0.w, n0, acc.w);
    }

    float dn = ISVAR ? g_inv[node] : g_isq[node];
    float4 o;
    o.x = fmaxf(acc.x * dn, 0.f); o.y = fmaxf(acc.y * dn, 0.f);
    o.z = fmaxf(acc.z * dn, 0.f); o.w = fmaxf(acc.w * dn, 0.f);
    float4* out = reinterpret_cast<float4*>(ISVAR ? g_h2v : g_h2m);
    stcs4(&out[(size_t)node * (HID / 4) + lane], o);
}

// ---------------- threefry-2x32 (JAX partitionable mode) -------------------
__device__ __forceinline__ uint32_t rotl32(uint32_t x, int r) {
    return __funnelshift_l(x, x, r);
}

__device__ __forceinline__ void threefry_42(uint32_t x0, uint32_t x1,
                                            uint32_t& o0, uint32_t& o1) {
    const uint32_t k0 = 0u, k1 = 42u;
    const uint32_t k2 = k0 ^ k1 ^ 0x1BD11BDAu;
    x0 += k0; x1 += k1;
#define TF_R4(a, b, c, d)                              \
    x0 += x1; x1 = rotl32(x1, a); x1 ^= x0;            \
    x0 += x1; x1 = rotl32(x1, b); x1 ^= x0;            \
    x0 += x1; x1 = rotl32(x1, c); x1 ^= x0;            \
    x0 += x1; x1 = rotl32(x1, d); x1 ^= x0;
    TF_R4(13, 15, 26, 6)  x0 += k1; x1 += k2 + 1u;
    TF_R4(17, 29, 16, 24) x0 += k2; x1 += k0 + 2u;
    TF_R4(13, 15, 26, 6)  x0 += k0; x1 += k1 + 3u;
    TF_R4(17, 29, 16, 24) x0 += k1; x1 += k2 + 4u;
    TF_R4(13, 15, 26, 6)  x0 += k2; x1 += k0 + 5u;
#undef TF_R4
    o0 = x0; o1 = x1;
}

__device__ __forceinline__ float bits_to_normal(uint32_t b) {
    float f = __uint_as_float((b >> 9) | 0x3F800000u) - 1.0f;
    const float LO = -0.99999994f;   // nextafter(-1, 0)
    float u = fmaf(f, 2.0f, LO);
    u = fmaxf(u, LO);
    return 1.41421356f * erfinvf(u);
}

// ---------------- layer-2 CSR aggregation + final epilogue -----------------
__global__ void __launch_bounds__(256)
agg2_final_kernel(float* __restrict__ out) {
    int node = (blockIdx.x * blockDim.x + threadIdx.x) >> 5;
    int lane = threadIdx.x & 31;
    if (node >= NN) return;
    int beg = g_ptr[node];
    int cnt = g_cnt[node];

    const float2* M = reinterpret_cast<const float2*>(g_m2);
    const float2* V = reinterpret_cast<const float2*>(g_v2);

    float2 am = make_float2(0.f, 0.f);
    float2 av = make_float2(0.f, 0.f);

    int i = 0;
    for (; i + 2 <= cnt; i += 2) {
        int s0 = __ldg(&g_esrc[beg + i]);
        int s1 = __ldg(&g_esrc[beg + i + 1]);
        float2 m0 = __ldg(&M[(size_t)s0 * (OUTF / 2) + lane]);
        float2 v0 = __ldg(&V[(size_t)s0 * (OUTF / 2) + lane]);
        float2 m1 = __ldg(&M[(size_t)s1 * (OUTF / 2) + lane]);
        float2 v1 = __ldg(&V[(size_t)s1 * (OUTF / 2) + lane]);
        am.x += m0.x + m1.x; am.y += m0.y + m1.y;
        av.x += v0.x + v1.x; av.y += v0.y + v1.y;
    }
    if (i < cnt) {
        int s0 = __ldg(&g_esrc[beg + i]);
        float2 m0 = __ldg(&M[(size_t)s0 * (OUTF / 2) + lane]);
        float2 v0 = __ldg(&V[(size_t)s0 * (OUTF / 2) + lane]);
        am.x += m0.x; am.y += m0.y;
        av.x += v0.x; av.y += v0.y;
    }

    float isq = g_isq[node], inv = g_inv[node];
    float mean0 = am.x * isq, mean1 = am.y * isq;
    float var0  = av.x * inv, var1  = av.y * inv;

    int j0 = node * OUTF + 2 * lane;
    uint32_t a0, a1, b0, b1;
    threefry_42(0u, (uint32_t)j0, a0, a1);
    threefry_42(0u, (uint32_t)(j0 + 1), b0, b1);
    float eps0 = bits_to_normal(a0 ^ a1);
    float eps1 = bits_to_normal(b0 ^ b1);

    float2 o;
    o.x = fmaf(eps0, sqrtf(var0 + 1e-8f), mean0);
    o.y = fmaf(eps1, sqrtf(var1 + 1e-8f), mean1);
    reinterpret_cast<float2*>(out)[(size_t)node * (OUTF / 2) + lane] = o;
}

// ---------------- launch ----------------------------------------------------
extern "C" void kernel_launch(void* const* d_in, const int* in_sizes, int n_in,
                              void* d_out, int out_size) {
    const float* x   = (const float*)d_in[0];
    const int* src   = (const int*)d_in[1];
    const int* dst   = (const int*)d_in[2];
    const float* wm1 = (const float*)d_in[3];
    const float* wv1 = (const float*)d_in[4];
    const float* bm1 = (const float*)d_in[5];
    const float* bv1 = (const float*)d_in[6];
    const float* wm2 = (const float*)d_in[7];
    const float* wv2 = (const float*)d_in[8];
    const float* bm2 = (const float*)d_in[9];
    const float* bv2 = (const float*)d_in[10];
    float* out = (float*)d_out;

    (void)in_sizes; (void)n_in; (void)out_size;

    float *p_h2m, *p_h2v, *p_m1, *p_v1, *p_m2, *p_v2;
    cudaGetSymbolAddress((void**)&p_m1, g_m1);
    cudaGetSymbolAddress((void**)&p_v1, g_v1);
    cudaGetSymbolAddress((void**)&p_h2m, g_h2m);
    cudaGetSymbolAddress((void**)&p_h2v, g_h2v);
    cudaGetSymbolAddress((void**)&p_m2, g_m2);
    cudaGetSymbolAddress((void**)&p_v2, g_v2);

    // persistent aux stream + fork/join events (created once; stream/event
    // creation is not a device allocation and is legal outside capture ops)
    static cudaStream_t s_aux = nullptr;
    static cudaEvent_t e_fork = nullptr, e_join = nullptr;
    if (!s_aux) {
        cudaStreamCreateWithFlags(&s_aux, cudaStreamNonBlocking);
        cudaEventCreateWithFlags(&e_fork, cudaEventDisableTiming);
        cudaEventCreateWithFlags(&e_join, cudaEventDisableTiming);
    }

    const int gridM = (NN + 127) / 128;
    const int agg_blocks = (NN * 32 + 255) / 256;

    // fork: CSR build chain on aux stream, GEMM1 (no norm dependency) on main
    cudaEventRecord(e_fork, 0);
    cudaStreamWaitEvent(s_aux, e_fork, 0);

    zero_cnt_kernel<<<(NN + 255) / 256, 256, 0, s_aux>>>();
    hist_kernel<<<(NE + 255) / 256, 256, 0, s_aux>>>(dst);
    scan1_kernel<<<NBLK, 1024, 0, s_aux>>>();
    scan2_kernel<<<1, 128, 0, s_aux>>>();
    scan3_kernel<<<(NN + 255) / 256, 256, 0, s_aux>>>();
    scatter_kernel<<<(NE + 255) / 256, 256, 0, s_aux>>>(src, dst);
    cudaEventRecord(e_join, s_aux);

    // layer 1: tf32 mma dual GEMM + msg epilogue (norm-free)
    gemm_dual_mma<16, true, false>
        <<<dim3(HID / 64, gridM), 256>>>(x, x, wm1, wv1, bm1, bv1,
                                         p_m1, p_v1, NN, F_IN, HID);

    // join: aggregation needs both GEMM1 output and the CSR + norms
    cudaStreamWaitEvent(0, e_join, 0);

    agg1_pass_kernel<false><<<agg_blocks, 256>>>();   // mean
    agg1_pass_kernel<true><<<agg_blocks, 256>>>();    // var

    // layer 2: tf32 mma dual GEMM (separate A's) + norm-prescaled msg epilogue
    gemm_dual_mma<16, false, true>
        <<<dim3(OUTF / 64, gridM), 256>>>(p_h2m, p_h2v, wm2, wv2, bm2, bv2,
                                          p_m2, p_v2, NN, HID, OUTF);

    agg2_final_kernel<<<agg_blocks, 256>>>(out);
}

// round 7
// speedup vs baseline: 3.5262x; 1.0981x over previous
#include <cuda_runtime.h>
#include <cuda_fp16.h>
#include <cstdint>

#define NN 100000
#define NE 1600000
#define F_IN 256
#define HID 128
#define OUTF 64
#define NBLK ((NN + 1023) / 1024)   // scan blocks = 98

// ---------------- scratch (device globals; no allocation allowed) ----------
__device__ int    g_cnt[NN];          // in-degree (histogram)
__device__ int    g_ptr[NN];          // CSR row start
__device__ int    g_cursor[NN];       // scatter cursors
__device__ int    g_esrc[NE];         // CSR: src indices grouped by dst
__device__ int    g_bsum[128];        // scan block sums
__device__ float  g_isq[NN];          // deg^-1/2
__device__ float  g_inv[NN];          // deg^-1
__device__ __half g_m1[NN * HID];     // layer-1 messages (mean*att), fp16
__device__ __half g_v1[NN * HID];     // layer-1 messages (var*att^2), fp16
__device__ float  g_h2m[NN * HID];    // layer-2 inputs (aggregated+relu)
__device__ float  g_h2v[NN * HID];
__device__ __half g_m2[NN * OUTF];    // layer-2 messages (norm-prescaled), fp16
__device__ __half g_v2[NN * OUTF];

// ---------------- CSR build --------------------------------------------------
__global__ void zero_cnt_kernel() {
    int i = blockIdx.x * blockDim.x + threadIdx.x;
    if (i < NN) g_cnt[i] = 0;
}

__global__ void hist_kernel(const int* __restrict__ dst) {
    int e = blockIdx.x * blockDim.x + threadIdx.x;
    if (e < NE) atomicAdd(&g_cnt[dst[e]], 1);
}

__global__ void scan1_kernel() {
    __shared__ int s[1024];
    int t = threadIdx.x;
    int i = blockIdx.x * 1024 + t;
    int v = (i < NN) ? g_cnt[i] : 0;
    s[t] = v;
    __syncthreads();
#pragma unroll
    for (int off = 1; off < 1024; off <<= 1) {
        int x = (t >= off) ? s[t - off] : 0;
        __syncthreads();
        s[t] += x;
        __syncthreads();
    }
    if (i < NN) g_ptr[i] = s[t] - v;
    if (t == 1023) g_bsum[blockIdx.x] = s[1023];
}

__global__ void scan2_kernel() {
    __shared__ int s[128];
    int t = threadIdx.x;
    s[t] = (t < NBLK) ? g_bsum[t] : 0;
    __syncthreads();
    if (t == 0) {
        int acc = 0;
        for (int b = 0; b < NBLK; b++) { int x = s[b]; s[b] = acc; acc += x; }
    }
    __syncthreads();
    if (t < NBLK) g_bsum[t] = s[t];
}

__global__ void scan3_kernel() {
    int i = blockIdx.x * blockDim.x + threadIdx.x;
    if (i >= NN) return;
    int p = g_ptr[i] + g_bsum[i >> 10];
    g_ptr[i] = p;
    g_cursor[i] = p;
    float d = fmaxf((float)g_cnt[i], 1.0f);
    float is = rsqrtf(d);
    g_isq[i] = is;
    g_inv[i] = is * is;
}

__global__ void scatter_kernel(const int* __restrict__ src,
                               const int* __restrict__ dst) {
    int e = blockIdx.x * blockDim.x + threadIdx.x;
    if (e >= NE) return;
    int d = dst[e];
    int pos = atomicAdd(&g_cursor[d], 1);
    g_esrc[pos] = src[e];
}

// ---------------- tf32 helpers ----------------------------------------------
__device__ __forceinline__ float to_tf32(float x) {
    uint32_t u;
    asm("cvt.rna.tf32.f32 %0, %1;" : "=r"(u) : "f"(x));
    return __uint_as_float(u);
}
__device__ __forceinline__ float4 to_tf32_4(float4 v) {
    v.x = to_tf32(v.x); v.y = to_tf32(v.y);
    v.z = to_tf32(v.z); v.w = to_tf32(v.w);
    return v;
}

__device__ __forceinline__ void mma_tf32(float* d, const uint32_t* a,
                                         uint32_t b0, uint32_t b1) {
    asm volatile(
        "mma.sync.aligned.m16n8k8.row.col.f32.tf32.tf32.f32 "
        "{%0,%1,%2,%3}, {%4,%5,%6,%7}, {%8,%9}, {%0,%1,%2,%3};"
        : "+f"(d[0]), "+f"(d[1]), "+f"(d[2]), "+f"(d[3])
        : "r"(a[0]), "r"(a[1]), "r"(a[2]), "r"(a[3]), "r"(b0), "r"(b1));
}

// ---------------- fused dual GEMM (tf32) + msg epilogue (fp16 out) ---------
// mean = relu(Am@Wm+bm), var = relu(Av@Wv+bv); att = exp(-var);
// NORM=true : Cm = mean*att*isq[row], Cv = var*att^2*inv[row]  (layer 2)
// NORM=false: Cm = mean*att,          Cv = var*att^2           (layer 1)
// Messages are written as __half2 (halves gather traffic downstream).
template <int BK, bool SAME_A, bool NORM>
__global__ void __launch_bounds__(256)
gemm_dual_mma(const float* __restrict__ Am, const float* __restrict__ Av,
              const float* __restrict__ Wm, const float* __restrict__ Wv,
              const float* __restrict__ biasm, const float* __restrict__ biasv,
              __half* __restrict__ Cm, __half* __restrict__ Cv,
              int M, int K, int N) {
    constexpr int BM = 128;
    constexpr int BN = 64;
    constexpr int AP = BK + 4;
    constexpr int BP = 72;
    constexpr int KSTEPS = BK / 8;

    __shared__ float Asm[2][BM][AP];
    __shared__ float Asv[SAME_A ? 1 : 2][SAME_A ? 1 : BM][SAME_A ? 1 : AP];
    __shared__ float Bsm[2][BK][BP];
    __shared__ float Bsv[2][BK][BP];

    const int tid = threadIdx.x;
    const int warp = tid >> 5;
    const int lane = tid & 31;
    const int g = lane >> 2;
    const int c = lane & 3;
    const int wm = warp & 3;
    const int wn = warp >> 2;
    const int wmBase = wm * 32;
    const int wnBase = wn * 32;

    const int col0 = blockIdx.x * BN;
    const int row0 = blockIdx.y * BM;

    constexpr int TPR = BK / 4;
    constexpr int AROWS = 256 / TPR;
    constexpr int APASS = BM / AROWS;
    const int a_r = tid / TPR;
    const int a_c = (tid % TPR) * 4;

    const int b_r = tid / 16;
    const int b_c = (tid % 16) * 4;
    const bool b_act = tid < BK * 16;

    float4 pam[APASS], pav[APASS], pbm, pbv;

    auto fetch = [&](int k0) {
        const float4 z = make_float4(0.f, 0.f, 0.f, 0.f);
#pragma unroll
        for (int p = 0; p < APASS; p++) {
            int gr = row0 + a_r + p * AROWS;
            pam[p] = (gr < M)
                ? *reinterpret_cast<const float4*>(&Am[(size_t)gr * K + k0 + a_c]) : z;
            if constexpr (!SAME_A)
                pav[p] = (gr < M)
                    ? *reinterpret_cast<const float4*>(&Av[(size_t)gr * K + k0 + a_c]) : z;
        }
        if (b_act) {
            pbm = *reinterpret_cast<const float4*>(&Wm[(size_t)(k0 + b_r) * N + col0 + b_c]);
            pbv = *reinterpret_cast<const float4*>(&Wv[(size_t)(k0 + b_r) * N + col0 + b_c]);
        }
    };
    auto sts = [&](int buf) {
#pragma unroll
        for (int p = 0; p < APASS; p++) {
            int r = a_r + p * AROWS;
            *reinterpret_cast<float4*>(&Asm[buf][r][a_c]) = to_tf32_4(pam[p]);
            if constexpr (!SAME_A)
                *reinterpret_cast<float4*>(&Asv[buf][r][a_c]) = to_tf32_4(pav[p]);
        }
        if (b_act) {
            *reinterpret_cast<float4*>(&Bsm[buf][b_r][b_c]) = to_tf32_4(pbm);
            *reinterpret_cast<float4*>(&Bsv[buf][b_r][b_c]) = to_tf32_4(pbv);
        }
    };

    float dm[2][4][4], dv[2][4][4];
#pragma unroll
    for (int mt = 0; mt < 2; mt++)
#pragma unroll
        for (int nt = 0; nt < 4; nt++)
#pragma unroll
            for (int r = 0; r < 4; r++) { dm[mt][nt][r] = 0.f; dv[mt][nt][r] = 0.f; }

    const int STEPS = K / BK;
    fetch(0);
    sts(0);
    __syncthreads();

    int buf = 0;
    for (int s = 0; s < STEPS; s++) {
        if (s + 1 < STEPS) fetch((s + 1) * BK);
#pragma unroll
        for (int kk = 0; kk < KSTEPS; kk++) {
            const int k0 = kk * 8;
            uint32_t am[2][4], av[2][4];
#pragma unroll
            for (int mt = 0; mt < 2; mt++) {
                int m0 = wmBase + mt * 16;
                am[mt][0] = __float_as_uint(Asm[buf][m0 + g][k0 + c]);
                am[mt][1] = __float_as_uint(Asm[buf][m0 + g + 8][k0 + c]);
                am[mt][2] = __float_as_uint(Asm[buf][m0 + g][k0 + c + 4]);
                am[mt][3] = __float_as_uint(Asm[buf][m0 + g + 8][k0 + c + 4]);
                if constexpr (!SAME_A) {
                    av[mt][0] = __float_as_uint(Asv[buf][m0 + g][k0 + c]);
                    av[mt][1] = __float_as_uint(Asv[buf][m0 + g + 8][k0 + c]);
                    av[mt][2] = __float_as_uint(Asv[buf][m0 + g][k0 + c + 4]);
                    av[mt][3] = __float_as_uint(Asv[buf][m0 + g + 8][k0 + c + 4]);
                }
            }
#pragma unroll
            for (int nt = 0; nt < 4; nt++) {
                int n0 = wnBase + nt * 8 + g;
                uint32_t bm0 = __float_as_uint(Bsm[buf][k0 + c][n0]);
                uint32_t bm1 = __float_as_uint(Bsm[buf][k0 + c + 4][n0]);
                uint32_t bv0 = __float_as_uint(Bsv[buf][k0 + c][n0]);
                uint32_t bv1 = __float_as_uint(Bsv[buf][k0 + c + 4][n0]);
#pragma unroll
                for (int mt = 0; mt < 2; mt++) {
                    mma_tf32(dm[mt][nt], am[mt], bm0, bm1);
                    if constexpr (SAME_A)
                        mma_tf32(dv[mt][nt], am[mt], bv0, bv1);
                    else
                        mma_tf32(dv[mt][nt], av[mt], bv0, bv1);
                }
            }
        }
        if (s + 1 < STEPS) {
            sts(buf ^ 1);
            __syncthreads();
            buf ^= 1;
        }
    }

    // epilogue: bias + relu + attention (+ norm) -> fp16 message stores
#pragma unroll
    for (int nt = 0; nt < 4; nt++) {
        int col = col0 + wnBase + nt * 8 + 2 * c;
        float2 bm2 = *reinterpret_cast<const float2*>(&biasm[col]);
        float2 bv2 = *reinterpret_cast<const float2*>(&biasv[col]);
#pragma unroll
        for (int mt = 0; mt < 2; mt++) {
            int r0 = row0 + wmBase + mt * 16 + g;
#pragma unroll
            for (int h = 0; h < 2; h++) {
                int r = r0 + h * 8;
                if (r >= M) continue;
                float isq = NORM ? g_isq[r] : 1.0f;
                float inv = NORM ? g_inv[r] : 1.0f;
                float mean0 = fmaxf(dm[mt][nt][2 * h + 0] + bm2.x, 0.f);
                float mean1 = fmaxf(dm[mt][nt][2 * h + 1] + bm2.y, 0.f);
                float var0  = fmaxf(dv[mt][nt][2 * h + 0] + bv2.x, 0.f);
                float var1  = fmaxf(dv[mt][nt][2 * h + 1] + bv2.y, 0.f);
                float att0 = expf(-var0);
                float att1 = expf(-var1);
                float om0, om1, ov0, ov1;
                if (NORM) {
                    om0 = mean0 * att0 * isq;  om1 = mean1 * att1 * isq;
                    ov0 = var0 * att0 * att0 * inv;
                    ov1 = var1 * att1 * att1 * inv;
                } else {
                    om0 = mean0 * att0;  om1 = mean1 * att1;
                    ov0 = var0 * att0 * att0;
                    ov1 = var1 * att1 * att1;
                }
                *reinterpret_cast<__half2*>(&Cm[(size_t)r * N + col]) =
                    __floats2half2_rn(om0, om1);
                *reinterpret_cast<__half2*>(&Cv[(size_t)r * N + col]) =
                    __floats2half2_rn(ov0, ov1);
            }
        }
    }
}

// ---------------- layer-1 CSR aggregation (split passes, fp16 gather) ------
// one warp per dst node; lane covers 4 dims (uint2 = 4 halfs). Gathered rows
// scaled by SRC node norm (fp32 fmaf). Output relu(sum*dst_norm), .cs stores.
__device__ __forceinline__ void stcs4(float4* p, float4 v) {
    asm volatile("st.global.cs.v4.f32 [%0], {%1,%2,%3,%4};"
                 :: "l"(p), "f"(v.x), "f"(v.y), "f"(v.z), "f"(v.w) : "memory");
}

template <bool ISVAR>
__global__ void __launch_bounds__(256)
agg1_pass_kernel() {
    int node = (blockIdx.x * blockDim.x + threadIdx.x) >> 5;
    int lane = threadIdx.x & 31;
    if (node >= NN) return;
    int beg = g_ptr[node];
    int cnt = g_cnt[node];

    const uint2* F = reinterpret_cast<const uint2*>(ISVAR ? g_v1 : g_m1);
    const float* SN = ISVAR ? g_inv : g_isq;
    // row = HID halfs = HID/4 uint2; lane's uint2 index = lane

    float4 acc = make_float4(0.f, 0.f, 0.f, 0.f);

    auto accum = [&](int s, float n) {
        uint2 raw = __ldg(&F[(size_t)s * (HID / 4) + lane]);
        __half2 h0 = *reinterpret_cast<const __half2*>(&raw.x);
        __half2 h1 = *reinterpret_cast<const __half2*>(&raw.y);
        float2 f0 = __half22float2(h0);
        float2 f1 = __half22float2(h1);
        acc.x = fmaf(f0.x, n, acc.x); acc.y = fmaf(f0.y, n, acc.y);
        acc.z = fmaf(f1.x, n, acc.z); acc.w = fmaf(f1.y, n, acc.w);
    };

    int i = 0;
    for (; i + 4 <= cnt; i += 4) {
        int s0 = __ldg(&g_esrc[beg + i]);
        int s1 = __ldg(&g_esrc[beg + i + 1]);
        int s2 = __ldg(&g_esrc[beg + i + 2]);
        int s3 = __ldg(&g_esrc[beg + i + 3]);
        float n0 = __ldg(&SN[s0]);
        float n1 = __ldg(&SN[s1]);
        float n2 = __ldg(&SN[s2]);
        float n3 = __ldg(&SN[s3]);
        accum(s0, n0); accum(s1, n1); accum(s2, n2); accum(s3, n3);
    }
    for (; i < cnt; i++) {
        int s0 = __ldg(&g_esrc[beg + i]);
        float n0 = __ldg(&SN[s0]);
        accum(s0, n0);
    }

    float dn = ISVAR ? g_inv[node] : g_isq[node];
    float4 o;
    o.x = fmaxf(acc.x * dn, 0.f); o.y = fmaxf(acc.y * dn, 0.f);
    o.z = fmaxf(acc.z * dn, 0.f); o.w = fmaxf(acc.w * dn, 0.f);
    float4* out = reinterpret_cast<float4*>(ISVAR ? g_h2v : g_h2m);
    stcs4(&out[(size_t)node * (HID / 4) + lane], o);
}

// ---------------- threefry-2x32 (JAX partitionable mode) -------------------
__device__ __forceinline__ uint32_t rotl32(uint32_t x, int r) {
    return __funnelshift_l(x, x, r);
}

__device__ __forceinline__ void threefry_42(uint32_t x0, uint32_t x1,
                                            uint32_t& o0, uint32_t& o1) {
    const uint32_t k0 = 0u, k1 = 42u;
    const uint32_t k2 = k0 ^ k1 ^ 0x1BD11BDAu;
    x0 += k0; x1 += k1;
#define TF_R4(a, b, c, d)                              \
    x0 += x1; x1 = rotl32(x1, a); x1 ^= x0;            \
    x0 += x1; x1 = rotl32(x1, b); x1 ^= x0;            \
    x0 += x1; x1 = rotl32(x1, c); x1 ^= x0;            \
    x0 += x1; x1 = rotl32(x1, d); x1 ^= x0;
    TF_R4(13, 15, 26, 6)  x0 += k1; x1 += k2 + 1u;
    TF_R4(17, 29, 16, 24) x0 += k2; x1 += k0 + 2u;
    TF_R4(13, 15, 26, 6)  x0 += k0; x1 += k1 + 3u;
    TF_R4(17, 29, 16, 24) x0 += k1; x1 += k2 + 4u;
    TF_R4(13, 15, 26, 6)  x0 += k2; x1 += k0 + 5u;
#undef TF_R4
    o0 = x0; o1 = x1;
}

__device__ __forceinline__ float bits_to_normal(uint32_t b) {
    float f = __uint_as_float((b >> 9) | 0x3F800000u) - 1.0f;
    const float LO = -0.99999994f;   // nextafter(-1, 0)
    float u = fmaf(f, 2.0f, LO);
    u = fmaxf(u, LO);
    return 1.41421356f * erfinvf(u);
}

// ---------------- layer-2 CSR aggregation + final epilogue (fp16 gather) ---
__global__ void __launch_bounds__(256)
agg2_final_kernel(float* __restrict__ out) {
    int node = (blockIdx.x * blockDim.x + threadIdx.x) >> 5;
    int lane = threadIdx.x & 31;
    if (node >= NN) return;
    int beg = g_ptr[node];
    int cnt = g_cnt[node];

    const uint32_t* M = reinterpret_cast<const uint32_t*>(g_m2);
    const uint32_t* V = reinterpret_cast<const uint32_t*>(g_v2);
    // row = OUTF halfs = OUTF/2 half2(uint); lane's index = lane

    float2 am = make_float2(0.f, 0.f);
    float2 av = make_float2(0.f, 0.f);

    auto accum = [&](int s) {
        uint32_t rm = __ldg(&M[(size_t)s * (OUTF / 2) + lane]);
        uint32_t rv = __ldg(&V[(size_t)s * (OUTF / 2) + lane]);
        float2 fm = __half22float2(*reinterpret_cast<const __half2*>(&rm));
        float2 fv = __half22float2(*reinterpret_cast<const __half2*>(&rv));
        am.x += fm.x; am.y += fm.y;
        av.x += fv.x; av.y += fv.y;
    };

    int i = 0;
    for (; i + 4 <= cnt; i += 4) {
        int s0 = __ldg(&g_esrc[beg + i]);
        int s1 = __ldg(&g_esrc[beg + i + 1]);
        int s2 = __ldg(&g_esrc[beg + i + 2]);
        int s3 = __ldg(&g_esrc[beg + i + 3]);
        accum(s0); accum(s1); accum(s2); accum(s3);
    }
    for (; i < cnt; i++) accum(__ldg(&g_esrc[beg + i]));

    float isq = g_isq[node], inv = g_inv[node];
    float mean0 = am.x * isq, mean1 = am.y * isq;
    float var0  = av.x * inv, var1  = av.y * inv;

    int j0 = node * OUTF + 2 * lane;
    uint32_t a0, a1, b0, b1;
    threefry_42(0u, (uint32_t)j0, a0, a1);
    threefry_42(0u, (uint32_t)(j0 + 1), b0, b1);
    float eps0 = bits_to_normal(a0 ^ a1);
    float eps1 = bits_to_normal(b0 ^ b1);

    float2 o;
    o.x = fmaf(eps0, sqrtf(var0 + 1e-8f), mean0);
    o.y = fmaf(eps1, sqrtf(var1 + 1e-8f), mean1);
    reinterpret_cast<float2*>(out)[(size_t)node * (OUTF / 2) + lane] = o;
}

// ---------------- launch ----------------------------------------------------
extern "C" void kernel_launch(void* const* d_in, const int* in_sizes, int n_in,
                              void* d_out, int out_size) {
    const float* x   = (const float*)d_in[0];
    const int* src   = (const int*)d_in[1];
    const int* dst   = (const int*)d_in[2];
    const float* wm1 = (const float*)d_in[3];
    const float* wv1 = (const float*)d_in[4];
    const float* bm1 = (const float*)d_in[5];
    const float* bv1 = (const float*)d_in[6];
    const float* wm2 = (const float*)d_in[7];
    const float* wv2 = (const float*)d_in[8];
    const float* bm2 = (const float*)d_in[9];
    const float* bv2 = (const float*)d_in[10];
    float* out = (float*)d_out;

    (void)in_sizes; (void)n_in; (void)out_size;

    float *p_h2m, *p_h2v;
    __half *p_m1, *p_v1, *p_m2, *p_v2;
    cudaGetSymbolAddress((void**)&p_m1, g_m1);
    cudaGetSymbolAddress((void**)&p_v1, g_v1);
    cudaGetSymbolAddress((void**)&p_h2m, g_h2m);
    cudaGetSymbolAddress((void**)&p_h2v, g_h2v);
    cudaGetSymbolAddress((void**)&p_m2, g_m2);
    cudaGetSymbolAddress((void**)&p_v2, g_v2);

    static cudaStream_t s_aux = nullptr;
    static cudaEvent_t e_fork = nullptr, e_join = nullptr;
    if (!s_aux) {
        cudaStreamCreateWithFlags(&s_aux, cudaStreamNonBlocking);
        cudaEventCreateWithFlags(&e_fork, cudaEventDisableTiming);
        cudaEventCreateWithFlags(&e_join, cudaEventDisableTiming);
    }

    const int gridM = (NN + 127) / 128;
    const int agg_blocks = (NN * 32 + 255) / 256;

    // fork: CSR build chain on aux stream, GEMM1 (no norm dependency) on main
    cudaEventRecord(e_fork, 0);
    cudaStreamWaitEvent(s_aux, e_fork, 0);

    zero_cnt_kernel<<<(NN + 255) / 256, 256, 0, s_aux>>>();
    hist_kernel<<<(NE + 255) / 256, 256, 0, s_aux>>>(dst);
    scan1_kernel<<<NBLK, 1024, 0, s_aux>>>();
    scan2_kernel<<<1, 128, 0, s_aux>>>();
    scan3_kernel<<<(NN + 255) / 256, 256, 0, s_aux>>>();
    scatter_kernel<<<(NE + 255) / 256, 256, 0, s_aux>>>(src, dst);
    cudaEventRecord(e_join, s_aux);

    // layer 1: tf32 mma dual GEMM + msg epilogue (norm-free, fp16 out)
    gemm_dual_mma<16, true, false>
        <<<dim3(HID / 64, gridM), 256>>>(x, x, wm1, wv1, bm1, bv1,
                                         p_m1, p_v1, NN, F_IN, HID);

    // join: aggregation needs both GEMM1 output and the CSR + norms
    cudaStreamWaitEvent(0, e_join, 0);

    agg1_pass_kernel<false><<<agg_blocks, 256>>>();   // mean
    agg1_pass_kernel<true><<<agg_blocks, 256>>>();    // var

    // layer 2: tf32 mma dual GEMM (separate A's) + norm-prescaled fp16 msgs
    gemm_dual_mma<16, false, true>
        <<<dim3(OUTF / 64, gridM), 256>>>(p_h2m, p_h2v, wm2, wv2, bm2, bv2,
                                          p_m2, p_v2, NN, HID, OUTF);

    agg2_final_kernel<<<agg_blocks, 256>>>(out);
}

// round 8
// speedup vs baseline: 4.0137x; 1.1382x over previous
#include <cuda_runtime.h>
#include <cuda_fp16.h>
#include <cstdint>

#define NN 100000
#define NE 1600000
#define F_IN 256
#define HID 128
#define OUTF 64
#define NBLK ((NN + 1023) / 1024)   // scan blocks = 98

// ---------------- scratch (device globals; no allocation allowed) ----------
__device__ int    g_cnt[NN];          // in-degree (histogram)
__device__ int    g_ptr[NN];          // CSR row start
__device__ int    g_cursor[NN];       // scatter cursors
__device__ int    g_esrc[NE];         // CSR: src indices grouped by dst
__device__ int    g_bsum[128];        // scan block sums
__device__ float  g_isq[NN];          // deg^-1/2
__device__ float  g_inv[NN];          // deg^-1
__device__ __half g_m1[NN * HID];     // layer-1 messages (mean*att), fp16
__device__ __half g_v1[NN * HID];     // layer-1 messages (var*att^2), fp16
__device__ float  g_h2m[NN * HID];    // layer-2 inputs (aggregated+relu)
__device__ float  g_h2v[NN * HID];
__device__ __half g_m2[NN * OUTF];    // layer-2 messages (norm-prescaled)
__device__ __half g_v2[NN * OUTF];

// ---------------- CSR build --------------------------------------------------
__global__ void zero_cnt_kernel() {
    int i = blockIdx.x * blockDim.x + threadIdx.x;
    if (i < NN) g_cnt[i] = 0;
}

__global__ void hist_kernel(const int* __restrict__ dst) {
    int e = blockIdx.x * blockDim.x + threadIdx.x;
    if (e < NE) atomicAdd(&g_cnt[dst[e]], 1);
}

__global__ void scan1_kernel() {
    __shared__ int s[1024];
    int t = threadIdx.x;
    int i = blockIdx.x * 1024 + t;
    int v = (i < NN) ? g_cnt[i] : 0;
    s[t] = v;
    __syncthreads();
#pragma unroll
    for (int off = 1; off < 1024; off <<= 1) {
        int x = (t >= off) ? s[t - off] : 0;
        __syncthreads();
        s[t] += x;
        __syncthreads();
    }
    if (i < NN) g_ptr[i] = s[t] - v;
    if (t == 1023) g_bsum[blockIdx.x] = s[1023];
}

__global__ void scan2_kernel() {
    __shared__ int s[128];
    int t = threadIdx.x;
    s[t] = (t < NBLK) ? g_bsum[t] : 0;
    __syncthreads();
    if (t == 0) {
        int acc = 0;
        for (int b = 0; b < NBLK; b++) { int x = s[b]; s[b] = acc; acc += x; }
    }
    __syncthreads();
    if (t < NBLK) g_bsum[t] = s[t];
}

__global__ void scan3_kernel() {
    int i = blockIdx.x * blockDim.x + threadIdx.x;
    if (i >= NN) return;
    int p = g_ptr[i] + g_bsum[i >> 10];
    g_ptr[i] = p;
    g_cursor[i] = p;
    float d = fmaxf((float)g_cnt[i], 1.0f);
    float is = rsqrtf(d);
    g_isq[i] = is;
    g_inv[i] = is * is;
}

__global__ void scatter_kernel(const int* __restrict__ src,
                               const int* __restrict__ dst) {
    int e = blockIdx.x * blockDim.x + threadIdx.x;
    if (e >= NE) return;
    int d = dst[e];
    int pos = atomicAdd(&g_cursor[d], 1);
    g_esrc[pos] = src[e];
}

// ---------------- fp16 MMA helpers ------------------------------------------
__device__ __forceinline__ uint2 f4_to_h4(float4 v) {
    __half2 lo = __floats2half2_rn(v.x, v.y);
    __half2 hi = __floats2half2_rn(v.z, v.w);
    uint2 r;
    r.x = *reinterpret_cast<uint32_t*>(&lo);
    r.y = *reinterpret_cast<uint32_t*>(&hi);
    return r;
}

__device__ __forceinline__ void ldsm_x4(uint32_t* r, uint32_t addr) {
    asm volatile("ldmatrix.sync.aligned.m8n8.x4.shared.b16 {%0,%1,%2,%3}, [%4];"
                 : "=r"(r[0]), "=r"(r[1]), "=r"(r[2]), "=r"(r[3]) : "r"(addr));
}
__device__ __forceinline__ void ldsm_x2_t(uint32_t& r0, uint32_t& r1, uint32_t addr) {
    asm volatile("ldmatrix.sync.aligned.m8n8.x2.trans.shared.b16 {%0,%1}, [%2];"
                 : "=r"(r0), "=r"(r1) : "r"(addr));
}
__device__ __forceinline__ void mma_f16(float* d, const uint32_t* a,
                                        uint32_t b0, uint32_t b1) {
    asm volatile(
        "mma.sync.aligned.m16n8k16.row.col.f32.f16.f16.f32 "
        "{%0,%1,%2,%3}, {%4,%5,%6,%7}, {%8,%9}, {%0,%1,%2,%3};"
        : "+f"(d[0]), "+f"(d[1]), "+f"(d[2]), "+f"(d[3])
        : "r"(a[0]), "r"(a[1]), "r"(a[2]), "r"(a[3]), "r"(b0), "r"(b1));
}

// ---------------- fused dual GEMM (fp16 HMMA) + msg epilogue ----------------
// mean = relu(Am@Wm+bm), var = relu(Av@Wv+bv); att = exp(-var);
// NORM=true : Cm = mean*att*isq[row], Cv = var*att^2*inv[row]  (layer 2)
// NORM=false: Cm = mean*att,          Cv = var*att^2           (layer 1)
// A row-major via ldmatrix.x4; B k-major via ldmatrix.x2.trans. fp32 accum.
template <int BK, bool SAME_A, bool NORM>
__global__ void __launch_bounds__(256)
gemm_dual_hmma(const float* __restrict__ Am, const float* __restrict__ Av,
               const float* __restrict__ Wm, const float* __restrict__ Wv,
               const float* __restrict__ biasm, const float* __restrict__ biasv,
               __half* __restrict__ Cm, __half* __restrict__ Cv,
               int M, int K, int N) {
    constexpr int BM = 128;
    constexpr int BN = 64;
    constexpr int AW = BK + 8;    // A row width in halfs (pad 8: conflict-free)
    constexpr int BW = BN + 8;    // B row width in halfs (72)
    constexpr int KSTEPS = BK / 16;

    __shared__ __half Ahm[2][BM][AW];
    __shared__ __half Ahv[SAME_A ? 1 : 2][SAME_A ? 1 : BM][SAME_A ? 1 : AW];
    __shared__ __half Bhm[2][BK][BW];
    __shared__ __half Bhv[2][BK][BW];

    const int tid = threadIdx.x;
    const int warp = tid >> 5;
    const int lane = tid & 31;
    const int g = lane >> 2;
    const int c = lane & 3;
    const int wm = warp & 3;
    const int wn = warp >> 2;
    const int wmBase = wm * 32;
    const int wnBase = wn * 32;

    const int col0 = blockIdx.x * BN;
    const int row0 = blockIdx.y * BM;

    // A loader: thread covers 4 k-contiguous floats of one row
    constexpr int TPR = BK / 4;
    constexpr int AROWS = 256 / TPR;
    constexpr int APASS = BM / AROWS;
    const int a_r = tid / TPR;
    const int a_c = (tid % TPR) * 4;

    // B loader: BK*16 float4s per matrix per step
    constexpr int BPASS = BK / 16;
    const int b_r = tid / 16;
    const int b_c = (tid % 16) * 4;

    float4 pam[APASS], pav[APASS], pbm[BPASS], pbv[BPASS];

    auto fetch = [&](int k0) {
        const float4 z = make_float4(0.f, 0.f, 0.f, 0.f);
#pragma unroll
        for (int p = 0; p < APASS; p++) {
            int gr = row0 + a_r + p * AROWS;
            pam[p] = (gr < M)
                ? *reinterpret_cast<const float4*>(&Am[(size_t)gr * K + k0 + a_c]) : z;
            if constexpr (!SAME_A)
                pav[p] = (gr < M)
                    ? *reinterpret_cast<const float4*>(&Av[(size_t)gr * K + k0 + a_c]) : z;
        }
#pragma unroll
        for (int p = 0; p < BPASS; p++) {
            int kr = b_r + p * 16;
            pbm[p] = *reinterpret_cast<const float4*>(&Wm[(size_t)(k0 + kr) * N + col0 + b_c]);
            pbv[p] = *reinterpret_cast<const float4*>(&Wv[(size_t)(k0 + kr) * N + col0 + b_c]);
        }
    };
    auto sts = [&](int buf) {
#pragma unroll
        for (int p = 0; p < APASS; p++) {
            int r = a_r + p * AROWS;
            *reinterpret_cast<uint2*>(&Ahm[buf][r][a_c]) = f4_to_h4(pam[p]);
            if constexpr (!SAME_A)
                *reinterpret_cast<uint2*>(&Ahv[buf][r][a_c]) = f4_to_h4(pav[p]);
        }
#pragma unroll
        for (int p = 0; p < BPASS; p++) {
            int kr = b_r + p * 16;
            *reinterpret_cast<uint2*>(&Bhm[buf][kr][b_c]) = f4_to_h4(pbm[p]);
            *reinterpret_cast<uint2*>(&Bhv[buf][kr][b_c]) = f4_to_h4(pbv[p]);
        }
    };

    // shared-space base addresses for ldmatrix
    const uint32_t aBaseM = (uint32_t)__cvta_generic_to_shared(&Ahm[0][0][0]);
    const uint32_t aBaseV = SAME_A ? aBaseM
        : (uint32_t)__cvta_generic_to_shared(&Ahv[0][0][0]);
    const uint32_t bBaseM = (uint32_t)__cvta_generic_to_shared(&Bhm[0][0][0]);
    const uint32_t bBaseV = (uint32_t)__cvta_generic_to_shared(&Bhv[0][0][0]);

    // per-lane ldmatrix geometry
    const int aRowLane = wmBase + (lane & 7) + ((lane >> 3) & 1) * 8; // + mt*16
    const int aColLane = (lane >> 4) * 8;                             // + k0
    const int bKLane = lane & 15;                                     // + k0

    float dm[2][4][4], dv[2][4][4];
#pragma unroll
    for (int mt = 0; mt < 2; mt++)
#pragma unroll
        for (int nt = 0; nt < 4; nt++)
#pragma unroll
            for (int r = 0; r < 4; r++) { dm[mt][nt][r] = 0.f; dv[mt][nt][r] = 0.f; }

    const int STEPS = K / BK;
    fetch(0);
    sts(0);
    __syncthreads();

    int buf = 0;
    for (int s = 0; s < STEPS; s++) {
        if (s + 1 < STEPS) fetch((s + 1) * BK);
#pragma unroll
        for (int kk = 0; kk < KSTEPS; kk++) {
            const int k0 = kk * 16;
            uint32_t am[2][4], av[2][4];
#pragma unroll
            for (int mt = 0; mt < 2; mt++) {
                uint32_t aoff = ((buf * BM + aRowLane + mt * 16) * AW
                                 + k0 + aColLane) * 2;
                ldsm_x4(am[mt], aBaseM + aoff);
                if constexpr (!SAME_A) ldsm_x4(av[mt], aBaseV + aoff);
            }
#pragma unroll
            for (int nt = 0; nt < 4; nt++) {
                uint32_t boff = ((buf * BK + k0 + bKLane) * BW
                                 + wnBase + nt * 8) * 2;
                uint32_t bm0, bm1, bv0, bv1;
                ldsm_x2_t(bm0, bm1, bBaseM + boff);
                ldsm_x2_t(bv0, bv1, bBaseV + boff);
#pragma unroll
                for (int mt = 0; mt < 2; mt++) {
                    mma_f16(dm[mt][nt], am[mt], bm0, bm1);
                    if constexpr (SAME_A)
                        mma_f16(dv[mt][nt], am[mt], bv0, bv1);
                    else
                        mma_f16(dv[mt][nt], av[mt], bv0, bv1);
                }
            }
        }
        if (s + 1 < STEPS) {
            sts(buf ^ 1);
            __syncthreads();
            buf ^= 1;
        }
    }

    // epilogue: bias + relu + attention (+ norm) -> fp16 message stores
#pragma unroll
    for (int nt = 0; nt < 4; nt++) {
        int col = col0 + wnBase + nt * 8 + 2 * c;
        float2 bm2 = *reinterpret_cast<const float2*>(&biasm[col]);
        float2 bv2 = *reinterpret_cast<const float2*>(&biasv[col]);
#pragma unroll
        for (int mt = 0; mt < 2; mt++) {
            int r0 = row0 + wmBase + mt * 16 + g;
#pragma unroll
            for (int h = 0; h < 2; h++) {
                int r = r0 + h * 8;
                if (r >= M) continue;
                float isq = NORM ? g_isq[r] : 1.0f;
                float inv = NORM ? g_inv[r] : 1.0f;
                float mean0 = fmaxf(dm[mt][nt][2 * h + 0] + bm2.x, 0.f);
                float mean1 = fmaxf(dm[mt][nt][2 * h + 1] + bm2.y, 0.f);
                float var0  = fmaxf(dv[mt][nt][2 * h + 0] + bv2.x, 0.f);
                float var1  = fmaxf(dv[mt][nt][2 * h + 1] + bv2.y, 0.f);
                float att0 = expf(-var0);
                float att1 = expf(-var1);
                float om0, om1, ov0, ov1;
                if (NORM) {
                    om0 = mean0 * att0 * isq;  om1 = mean1 * att1 * isq;
                    ov0 = var0 * att0 * att0 * inv;
                    ov1 = var1 * att1 * att1 * inv;
                } else {
                    om0 = mean0 * att0;  om1 = mean1 * att1;
                    ov0 = var0 * att0 * att0;
                    ov1 = var1 * att1 * att1;
                }
                *reinterpret_cast<__half2*>(&Cm[(size_t)r * N + col]) =
                    __floats2half2_rn(om0, om1);
                *reinterpret_cast<__half2*>(&Cv[(size_t)r * N + col]) =
                    __floats2half2_rn(ov0, ov1);
            }
        }
    }
}

// ---------------- layer-1 CSR aggregation (merged mean+var, fp16 gather) ---
// one warp per dst node; lane covers 4 dims of each matrix (uint2 = 4 halfs).
// Gathered rows scaled by SRC node norms (fp32 fmaf). relu(sum*dst_norm) out.
__device__ __forceinline__ void stcs4(float4* p, float4 v) {
    asm volatile("st.global.cs.v4.f32 [%0], {%1,%2,%3,%4};"
                 :: "l"(p), "f"(v.x), "f"(v.y), "f"(v.z), "f"(v.w) : "memory");
}

__global__ void __launch_bounds__(256)
agg1_kernel() {
    int node = (blockIdx.x * blockDim.x + threadIdx.x) >> 5;
    int lane = threadIdx.x & 31;
    if (node >= NN) return;
    int beg = g_ptr[node];
    int cnt = g_cnt[node];

    const uint2* M = reinterpret_cast<const uint2*>(g_m1);
    const uint2* V = reinterpret_cast<const uint2*>(g_v1);

    float4 am = make_float4(0.f, 0.f, 0.f, 0.f);
    float4 av = make_float4(0.f, 0.f, 0.f, 0.f);

    auto accum = [&](int s, float nisq, float ninv) {
        uint2 rm = __ldg(&M[(size_t)s * (HID / 4) + lane]);
        uint2 rv = __ldg(&V[(size_t)s * (HID / 4) + lane]);
        float2 m0 = __half22float2(*reinterpret_cast<const __half2*>(&rm.x));
        float2 m1 = __half22float2(*reinterpret_cast<const __half2*>(&rm.y));
        float2 v0 = __half22float2(*reinterpret_cast<const __half2*>(&rv.x));
        float2 v1 = __half22float2(*reinterpret_cast<const __half2*>(&rv.y));
        am.x = fmaf(m0.x, nisq, am.x); am.y = fmaf(m0.y, nisq, am.y);
        am.z = fmaf(m1.x, nisq, am.z); am.w = fmaf(m1.y, nisq, am.w);
        av.x = fmaf(v0.x, ninv, av.x); av.y = fmaf(v0.y, ninv, av.y);
        av.z = fmaf(v1.x, ninv, av.z); av.w = fmaf(v1.y, ninv, av.w);
    };

    int i = 0;
    for (; i + 2 <= cnt; i += 2) {
        int s0 = __ldg(&g_esrc[beg + i]);
        int s1 = __ldg(&g_esrc[beg + i + 1]);
        float q0 = __ldg(&g_isq[s0]);
        float p0 = __ldg(&g_inv[s0]);
        float q1 = __ldg(&g_isq[s1]);
        float p1 = __ldg(&g_inv[s1]);
        accum(s0, q0, p0);
        accum(s1, q1, p1);
    }
    if (i < cnt) {
        int s0 = __ldg(&g_esrc[beg + i]);
        accum(s0, __ldg(&g_isq[s0]), __ldg(&g_inv[s0]));
    }

    float isq = g_isq[node], inv = g_inv[node];
    float4 om, ov;
    om.x = fmaxf(am.x * isq, 0.f); om.y = fmaxf(am.y * isq, 0.f);
    om.z = fmaxf(am.z * isq, 0.f); om.w = fmaxf(am.w * isq, 0.f);
    ov.x = fmaxf(av.x * inv, 0.f); ov.y = fmaxf(av.y * inv, 0.f);
    ov.z = fmaxf(av.z * inv, 0.f); ov.w = fmaxf(av.w * inv, 0.f);
    stcs4(&reinterpret_cast<float4*>(g_h2m)[(size_t)node * (HID / 4) + lane], om);
    stcs4(&reinterpret_cast<float4*>(g_h2v)[(size_t)node * (HID / 4) + lane], ov);
}

// ---------------- threefry-2x32 (JAX partitionable mode) -------------------
__device__ __forceinline__ uint32_t rotl32(uint32_t x, int r) {
    return __funnelshift_l(x, x, r);
}

__device__ __forceinline__ void threefry_42(uint32_t x0, uint32_t x1,
                                            uint32_t& o0, uint32_t& o1) {
    const uint32_t k0 = 0u, k1 = 42u;
    const uint32_t k2 = k0 ^ k1 ^ 0x1BD11BDAu;
    x0 += k0; x1 += k1;
#define TF_R4(a, b, c, d)                              \
    x0 += x1; x1 = rotl32(x1, a); x1 ^= x0;            \
    x0 += x1; x1 = rotl32(x1, b); x1 ^= x0;            \
    x0 += x1; x1 = rotl32(x1, c); x1 ^= x0;            \
    x0 += x1; x1 = rotl32(x1, d); x1 ^= x0;
    TF_R4(13, 15, 26, 6)  x0 += k1; x1 += k2 + 1u;
    TF_R4(17, 29, 16, 24) x0 += k2; x1 += k0 + 2u;
    TF_R4(13, 15, 26, 6)  x0 += k0; x1 += k1 + 3u;
    TF_R4(17, 29, 16, 24) x0 += k1; x1 += k2 + 4u;
    TF_R4(13, 15, 26, 6)  x0 += k2; x1 += k0 + 5u;
#undef TF_R4
    o0 = x0; o1 = x1;
}

__device__ __forceinline__ float bits_to_normal(uint32_t b) {
    float f = __uint_as_float((b >> 9) | 0x3F800000u) - 1.0f;
    const float LO = -0.99999994f;   // nextafter(-1, 0)
    float u = fmaf(f, 2.0f, LO);
    u = fmaxf(u, LO);
    return 1.41421356f * erfinvf(u);
}

// ---------------- layer-2 CSR aggregation + final epilogue (fp16 gather) ---
__global__ void __launch_bounds__(256)
agg2_final_kernel(float* __restrict__ out) {
    int node = (blockIdx.x * blockDim.x + threadIdx.x) >> 5;
    int lane = threadIdx.x & 31;
    if (node >= NN) return;
    int beg = g_ptr[node];
    int cnt = g_cnt[node];

    const uint32_t* M = reinterpret_cast<const uint32_t*>(g_m2);
    const uint32_t* V = reinterpret_cast<const uint32_t*>(g_v2);

    float2 am = make_float2(0.f, 0.f);
    float2 av = make_float2(0.f, 0.f);

    auto accum = [&](int s) {
        uint32_t rm = __ldg(&M[(size_t)s * (OUTF / 2) + lane]);
        uint32_t rv = __ldg(&V[(size_t)s * (OUTF / 2) + lane]);
        float2 fm = __half22float2(*reinterpret_cast<const __half2*>(&rm));
        float2 fv = __half22float2(*reinterpret_cast<const __half2*>(&rv));
        am.x += fm.x; am.y += fm.y;
        av.x += fv.x; av.y += fv.y;
    };

    int i = 0;
    for (; i + 4 <= cnt; i += 4) {
        int s0 = __ldg(&g_esrc[beg + i]);
        int s1 = __ldg(&g_esrc[beg + i + 1]);
        int s2 = __ldg(&g_esrc[beg + i + 2]);
        int s3 = __ldg(&g_esrc[beg + i + 3]);
        accum(s0); accum(s1); accum(s2); accum(s3);
    }
    for (; i < cnt; i++) accum(__ldg(&g_esrc[beg + i]));

    float isq = g_isq[node], inv = g_inv[node];
    float mean0 = am.x * isq, mean1 = am.y * isq;
    float var0  = av.x * inv, var1  = av.y * inv;

    int j0 = node * OUTF + 2 * lane;
    uint32_t a0, a1, b0, b1;
    threefry_42(0u, (uint32_t)j0, a0, a1);
    threefry_42(0u, (uint32_t)(j0 + 1), b0, b1);
    float eps0 = bits_to_normal(a0 ^ a1);
    float eps1 = bits_to_normal(b0 ^ b1);

    float2 o;
    o.x = fmaf(eps0, sqrtf(var0 + 1e-8f), mean0);
    o.y = fmaf(eps1, sqrtf(var1 + 1e-8f), mean1);
    reinterpret_cast<float2*>(out)[(size_t)node * (OUTF / 2) + lane] = o;
}

// ---------------- launch ----------------------------------------------------
extern "C" void kernel_launch(void* const* d_in, const int* in_sizes, int n_in,
                              void* d_out, int out_size) {
    const float* x   = (const float*)d_in[0];
    const int* src   = (const int*)d_in[1];
    const int* dst   = (const int*)d_in[2];
    const float* wm1 = (const float*)d_in[3];
    const float* wv1 = (const float*)d_in[4];
    const float* bm1 = (const float*)d_in[5];
    const float* bv1 = (const float*)d_in[6];
    const float* wm2 = (const float*)d_in[7];
    const float* wv2 = (const float*)d_in[8];
    const float* bm2 = (const float*)d_in[9];
    const float* bv2 = (const float*)d_in[10];
    float* out = (float*)d_out;

    (void)in_sizes; (void)n_in; (void)out_size;

    float *p_h2m, *p_h2v;
    __half *p_m1, *p_v1, *p_m2, *p_v2;
    cudaGetSymbolAddress((void**)&p_m1, g_m1);
    cudaGetSymbolAddress((void**)&p_v1, g_v1);
    cudaGetSymbolAddress((void**)&p_h2m, g_h2m);
    cudaGetSymbolAddress((void**)&p_h2v, g_h2v);
    cudaGetSymbolAddress((void**)&p_m2, g_m2);
    cudaGetSymbolAddress((void**)&p_v2, g_v2);

    static cudaStream_t s_aux = nullptr;
    static cudaEvent_t e_fork = nullptr, e_join = nullptr;
    if (!s_aux) {
        cudaStreamCreateWithFlags(&s_aux, cudaStreamNonBlocking);
        cudaEventCreateWithFlags(&e_fork, cudaEventDisableTiming);
        cudaEventCreateWithFlags(&e_join, cudaEventDisableTiming);
    }

    const int gridM = (NN + 127) / 128;
    const int agg_blocks = (NN * 32 + 255) / 256;

    // fork: CSR build chain on aux stream, GEMM1 (no norm dependency) on main
    cudaEventRecord(e_fork, 0);
    cudaStreamWaitEvent(s_aux, e_fork, 0);

    zero_cnt_kernel<<<(NN + 255) / 256, 256, 0, s_aux>>>();
    hist_kernel<<<(NE + 255) / 256, 256, 0, s_aux>>>(dst);
    scan1_kernel<<<NBLK, 1024, 0, s_aux>>>();
    scan2_kernel<<<1, 128, 0, s_aux>>>();
    scan3_kernel<<<(NN + 255) / 256, 256, 0, s_aux>>>();
    scatter_kernel<<<(NE + 255) / 256, 256, 0, s_aux>>>(src, dst);
    cudaEventRecord(e_join, s_aux);

    // layer 1: fp16 HMMA dual GEMM + msg epilogue (norm-free, fp16 out)
    gemm_dual_hmma<32, true, false>
        <<<dim3(HID / 64, gridM), 256>>>(x, x, wm1, wv1, bm1, bv1,
                                         p_m1, p_v1, NN, F_IN, HID);

    // join: aggregation needs both GEMM1 output and the CSR + norms
    cudaStreamWaitEvent(0, e_join, 0);

    // layer 1 aggregation (merged mean+var) + relu(sum*norm)
    agg1_kernel<<<agg_blocks, 256>>>();

    // layer 2: fp16 HMMA dual GEMM (separate A's) + norm-prescaled fp16 msgs
    gemm_dual_hmma<16, false, true>
        <<<dim3(OUTF / 64, gridM), 256>>>(p_h2m, p_h2v, wm2, wv2, bm2, bv2,
                                          p_m2, p_v2, NN, HID, OUTF);

    agg2_final_kernel<<<agg_blocks, 256>>>(out);
}